// round 2
// baseline (speedup 1.0000x reference)
#include <cuda_runtime.h>
#include <math.h>
#include <float.h>

// Attention with bias + causal mask.
// q,k,v: [B,H,N,D] fp32 ; bias: [B,H,N,N] fp32 ; out: [B,H,N,D] fp32
// B=4, H=16, N=1024, D=64.

#define BN_ 1024      // sequence length N
#define DD_ 64        // head dim
#define BH_ 64        // B*H
#define BM 64         // query rows per CTA
#define BNT 64        // key cols per tile
#define SQ 68         // smem row stride (floats): 64 + 4 pad, keeps 16B alignment

__global__ __launch_bounds__(256)
void attn_fwd_kernel(const float* __restrict__ q,
                     const float* __restrict__ k,
                     const float* __restrict__ v,
                     const float* __restrict__ bias,
                     float* __restrict__ out)
{
    extern __shared__ float smem[];
    float* Qt = smem;                 // [D][BM]  d-major, stride SQ
    float* Kt = Qt + DD_ * SQ;        // [D][BNT] d-major, stride SQ
    float* Vs = Kt + DD_ * SQ;        // [BNT][D] row-major, stride SQ
    float* Ps = Vs + BNT * SQ;        // [BNT][BM] P transposed (col-major P), stride SQ

    const int tid = threadIdx.x;
    const int tx  = tid & 15;         // 16 column-groups
    const int ty  = tid >> 4;         // 16 row-groups
    const int r0  = ty * 4;           // local rows  [r0, r0+4)
    const int c0  = tx * 4;           // local cols / dims [c0, c0+4)

    const int m  = blockIdx.x;        // query tile index (0..15)
    const int bh = blockIdx.y;        // fused batch*head (0..63)

    const float scale = 0.125f;       // 1/sqrt(64)

    const float* qp = q + ((size_t)bh * BN_ + (size_t)m * BM) * DD_;
    const float* op_base = out + ((size_t)bh * BN_ + (size_t)m * BM) * DD_;

    // ---- load Q tile transposed into smem: Qt[d][r] ----
    #pragma unroll
    for (int t = 0; t < 4; ++t) {
        int idx = tid + t * 256;          // 1024 float4 loads total
        int row = idx >> 4;               // 0..63
        int d4  = (idx & 15) * 4;         // 0,4,...,60
        float4 val = *reinterpret_cast<const float4*>(qp + row * DD_ + d4);
        Qt[(d4 + 0) * SQ + row] = val.x;
        Qt[(d4 + 1) * SQ + row] = val.y;
        Qt[(d4 + 2) * SQ + row] = val.z;
        Qt[(d4 + 3) * SQ + row] = val.w;
    }

    // per-row softmax state (rows r0..r0+3), replicated across the 16 tx lanes
    float mrow[4], lrow[4];
    float acc[4][4];
    #pragma unroll
    for (int i = 0; i < 4; ++i) {
        mrow[i] = -INFINITY;
        lrow[i] = 0.f;
        #pragma unroll
        for (int j = 0; j < 4; ++j) acc[i][j] = 0.f;
    }

    const int ntiles = m + 1;   // causal: only key tiles n <= m

    for (int n = 0; n < ntiles; ++n) {
        __syncthreads();   // previous iteration's smem reads complete

        // ---- load K tile transposed, V tile row-major ----
        const float* kp = k + ((size_t)bh * BN_ + (size_t)n * BNT) * DD_;
        const float* vp = v + ((size_t)bh * BN_ + (size_t)n * BNT) * DD_;
        #pragma unroll
        for (int t = 0; t < 4; ++t) {
            int idx = tid + t * 256;
            int row = idx >> 4;
            int d4  = (idx & 15) * 4;
            float4 kv = *reinterpret_cast<const float4*>(kp + row * DD_ + d4);
            Kt[(d4 + 0) * SQ + row] = kv.x;
            Kt[(d4 + 1) * SQ + row] = kv.y;
            Kt[(d4 + 2) * SQ + row] = kv.z;
            Kt[(d4 + 3) * SQ + row] = kv.w;
            float4 vv = *reinterpret_cast<const float4*>(vp + row * DD_ + d4);
            *reinterpret_cast<float4*>(&Vs[row * SQ + d4]) = vv;
        }
        __syncthreads();

        // ---- S = Q K^T (4x4 micro-tile per thread) ----
        float s[4][4];
        #pragma unroll
        for (int i = 0; i < 4; ++i)
            #pragma unroll
            for (int j = 0; j < 4; ++j) s[i][j] = 0.f;

        #pragma unroll 8
        for (int d = 0; d < DD_; ++d) {
            float4 q4 = *reinterpret_cast<const float4*>(&Qt[d * SQ + r0]);
            float4 k4 = *reinterpret_cast<const float4*>(&Kt[d * SQ + c0]);
            const float qa[4] = {q4.x, q4.y, q4.z, q4.w};
            const float ka[4] = {k4.x, k4.y, k4.z, k4.w};
            #pragma unroll
            for (int i = 0; i < 4; ++i)
                #pragma unroll
                for (int j = 0; j < 4; ++j)
                    s[i][j] = fmaf(qa[i], ka[j], s[i][j]);
        }

        // ---- scale + bias (direct coalesced gmem read) + causal mask ----
        const bool diag = (n == m);
        #pragma unroll
        for (int i = 0; i < 4; ++i) {
            int grow = m * BM + r0 + i;
            const float* bp = bias + ((size_t)bh * BN_ + grow) * BN_ + (size_t)n * BNT + c0;
            float4 b4 = *reinterpret_cast<const float4*>(bp);
            const float ba[4] = {b4.x, b4.y, b4.z, b4.w};
            #pragma unroll
            for (int j = 0; j < 4; ++j) {
                float sv = s[i][j] * scale + ba[j];
                if (diag) {
                    int gcol = n * BNT + c0 + j;
                    if (gcol > grow) sv = -INFINITY;
                }
                s[i][j] = sv;
            }
        }

        // ---- online softmax per row ----
        #pragma unroll
        for (int i = 0; i < 4; ++i) {
            float tmax = fmaxf(fmaxf(s[i][0], s[i][1]), fmaxf(s[i][2], s[i][3]));
            #pragma unroll
            for (int o = 1; o < 16; o <<= 1)
                tmax = fmaxf(tmax, __shfl_xor_sync(0xffffffffu, tmax, o));
            float mnew = fmaxf(mrow[i], tmax);
            float corr = __expf(mrow[i] - mnew);   // 0 on first tile (-inf - finite)
            mrow[i] = mnew;

            float psum = 0.f;
            #pragma unroll
            for (int j = 0; j < 4; ++j) {
                float p = __expf(s[i][j] - mnew);
                s[i][j] = p;
                psum += p;
            }
            #pragma unroll
            for (int o = 1; o < 16; o <<= 1)
                psum += __shfl_xor_sync(0xffffffffu, psum, o);

            lrow[i] = lrow[i] * corr + psum;
            #pragma unroll
            for (int j = 0; j < 4; ++j) acc[i][j] *= corr;
        }

        // ---- stash P transposed: Ps[c][r] ----
        #pragma unroll
        for (int i = 0; i < 4; ++i)
            #pragma unroll
            for (int j = 0; j < 4; ++j)
                Ps[(c0 + j) * SQ + (r0 + i)] = s[i][j];
        __syncthreads();

        // ---- O += P V (outer product over key index c) ----
        #pragma unroll 8
        for (int c = 0; c < BNT; ++c) {
            float4 p4 = *reinterpret_cast<const float4*>(&Ps[c * SQ + r0]);
            float4 v4 = *reinterpret_cast<const float4*>(&Vs[c * SQ + c0]);
            const float pa[4] = {p4.x, p4.y, p4.z, p4.w};
            const float va[4] = {v4.x, v4.y, v4.z, v4.w};
            #pragma unroll
            for (int i = 0; i < 4; ++i)
                #pragma unroll
                for (int j = 0; j < 4; ++j)
                    acc[i][j] = fmaf(pa[i], va[j], acc[i][j]);
        }
    }

    // ---- normalize and write out ----
    #pragma unroll
    for (int i = 0; i < 4; ++i) {
        float inv = 1.f / lrow[i];
        float4 o4;
        o4.x = acc[i][0] * inv;
        o4.y = acc[i][1] * inv;
        o4.z = acc[i][2] * inv;
        o4.w = acc[i][3] * inv;
        *reinterpret_cast<float4*>(const_cast<float*>(op_base) + (r0 + i) * DD_ + c0) = o4;
    }
}

extern "C" void kernel_launch(void* const* d_in, const int* in_sizes, int n_in,
                              void* d_out, int out_size)
{
    const float* q    = (const float*)d_in[0];
    const float* k    = (const float*)d_in[1];
    const float* v    = (const float*)d_in[2];
    const float* bias = (const float*)d_in[3];
    float* out = (float*)d_out;

    const int smem_bytes = 4 * DD_ * SQ * sizeof(float);  // Qt,Kt,Vs,Ps = 69632 B
    cudaFuncSetAttribute(attn_fwd_kernel,
                         cudaFuncAttributeMaxDynamicSharedMemorySize, smem_bytes);

    dim3 grid(BN_ / BM, BH_);   // (16, 64)
    dim3 block(256);
    attn_fwd_kernel<<<grid, block, smem_bytes>>>(q, k, v, bias, out);
}

// round 3
// speedup vs baseline: 1.1082x; 1.1082x over previous
#include <cuda_runtime.h>
#include <math.h>
#include <float.h>

// Attention with bias + causal mask, fp32.
// q,k,v: [B,H,N,D]; bias: [B,H,N,N]; out: [B,H,N,D]. B=4,H=16,N=1024,D=64.
// BM=128 query rows per CTA, BKT=64 keys per tile, 256 threads,
// 8x4 register micro-tile, packed fma.rn.f32x2 (row pairs).

#define SEQ 1024
#define DD  64
#define NBH 64
#define BM  128
#define BKT 64
#define SQ1 132   // stride for [D][BM] tiles (Qt, Ps): 128+4 pad
#define SKV 68    // stride for 64-wide tiles (Kt, Vs): 64+4 pad

typedef unsigned long long u64;

__device__ __forceinline__ u64 pack2(float lo, float hi) {
    u64 r; asm("mov.b64 %0, {%1,%2};" : "=l"(r) : "f"(lo), "f"(hi)); return r;
}
__device__ __forceinline__ u64 dup2(float x) { return pack2(x, x); }
__device__ __forceinline__ void fma2(u64& d, u64 a, u64 b) {
    asm("fma.rn.f32x2 %0, %1, %2, %0;" : "+l"(d) : "l"(a), "l"(b));
}
__device__ __forceinline__ u64 mul2(u64 a, u64 b) {
    u64 r; asm("mul.rn.f32x2 %0, %1, %2;" : "=l"(r) : "l"(a), "l"(b)); return r;
}
__device__ __forceinline__ float lo2(u64 x) { return __uint_as_float((unsigned)x); }
__device__ __forceinline__ float hi2(u64 x) { return __uint_as_float((unsigned)(x >> 32)); }

__global__ __launch_bounds__(256, 2)
void attn_fwd_kernel(const float* __restrict__ q,
                     const float* __restrict__ k,
                     const float* __restrict__ v,
                     const float* __restrict__ bias,
                     float* __restrict__ out)
{
    extern __shared__ float smem[];
    float* Qt = smem;                  // [DD][BM]  d-major, stride SQ1 (scale folded in)
    float* Kt = Qt + DD * SQ1;         // [DD][BKT] d-major, stride SKV
    float* Vs = Kt + DD * SKV;         // [BKT][DD] row-major, stride SKV
    float* Ps = Vs + BKT * SKV;        // [BKT][BM] P transposed, stride SQ1

    const int tid = threadIdx.x;
    const int tx  = tid & 15;          // 16 col groups (4 cols each)
    const int ty  = tid >> 4;          // 16 row groups (8 rows each)
    const int r0  = ty * 8;
    const int c0  = tx * 4;

    const int m  = blockIdx.x;         // query tile 0..7
    const int bh = blockIdx.y;         // batch*head 0..63

    const float* qp = q + ((size_t)bh * SEQ + (size_t)m * BM) * DD;
    float* op = out + ((size_t)bh * SEQ + (size_t)m * BM) * DD;

    // ---- load Q transposed, scale folded: Qt[d][r] = Q[r][d] * 0.125 ----
    #pragma unroll
    for (int t = 0; t < 8; ++t) {
        int idx = tid + t * 256;           // 2048 float4
        int row = idx >> 4;                // 0..127
        int d4  = (idx & 15) * 4;
        float4 val = *reinterpret_cast<const float4*>(qp + row * DD + d4);
        Qt[(d4 + 0) * SQ1 + row] = val.x * 0.125f;
        Qt[(d4 + 1) * SQ1 + row] = val.y * 0.125f;
        Qt[(d4 + 2) * SQ1 + row] = val.z * 0.125f;
        Qt[(d4 + 3) * SQ1 + row] = val.w * 0.125f;
    }

    u64 acc2[4][4];                    // row-pairs (2i,2i+1) x 4 cols of output dims
    float mrow[8], lrow[8];
    #pragma unroll
    for (int i = 0; i < 4; ++i)
        #pragma unroll
        for (int j = 0; j < 4; ++j) acc2[i][j] = 0ULL;
    #pragma unroll
    for (int i = 0; i < 8; ++i) { mrow[i] = -INFINITY; lrow[i] = 0.f; }

    const int ntiles = 2 * m + 2;      // causal: key tiles covering cols <= last row

    for (int n = 0; n < ntiles; ++n) {
        __syncthreads();

        // ---- stage K transposed + V row-major ----
        const float* kp = k + ((size_t)bh * SEQ + (size_t)n * BKT) * DD;
        const float* vp = v + ((size_t)bh * SEQ + (size_t)n * BKT) * DD;
        #pragma unroll
        for (int t = 0; t < 4; ++t) {
            int idx = tid + t * 256;       // 1024 float4 each
            int row = idx >> 4;            // 0..63
            int d4  = (idx & 15) * 4;
            float4 kv = *reinterpret_cast<const float4*>(kp + row * DD + d4);
            Kt[(d4 + 0) * SKV + row] = kv.x;
            Kt[(d4 + 1) * SKV + row] = kv.y;
            Kt[(d4 + 2) * SKV + row] = kv.z;
            Kt[(d4 + 3) * SKV + row] = kv.w;
            float4 vv = *reinterpret_cast<const float4*>(vp + row * DD + d4);
            *reinterpret_cast<float4*>(&Vs[row * SKV + d4]) = vv;
        }
        __syncthreads();

        // ---- S = (Q*scale) K^T, packed row pairs ----
        u64 s2[4][4];
        #pragma unroll
        for (int i = 0; i < 4; ++i)
            #pragma unroll
            for (int j = 0; j < 4; ++j) s2[i][j] = 0ULL;

        #pragma unroll 8
        for (int d = 0; d < DD; ++d) {
            float4 qa = *reinterpret_cast<const float4*>(&Qt[d * SQ1 + r0]);
            float4 qb = *reinterpret_cast<const float4*>(&Qt[d * SQ1 + r0 + 4]);
            u64 qq[4] = { pack2(qa.x, qa.y), pack2(qa.z, qa.w),
                          pack2(qb.x, qb.y), pack2(qb.z, qb.w) };
            float4 kv = *reinterpret_cast<const float4*>(&Kt[d * SKV + c0]);
            u64 kk[4] = { dup2(kv.x), dup2(kv.y), dup2(kv.z), dup2(kv.w) };
            #pragma unroll
            for (int i = 0; i < 4; ++i)
                #pragma unroll
                for (int j = 0; j < 4; ++j)
                    fma2(s2[i][j], qq[i], kk[j]);
        }

        // ---- unpack, + bias, causal mask ----
        float sv[8][4];
        #pragma unroll
        for (int i = 0; i < 4; ++i)
            #pragma unroll
            for (int j = 0; j < 4; ++j) {
                sv[2 * i + 0][j] = lo2(s2[i][j]);
                sv[2 * i + 1][j] = hi2(s2[i][j]);
            }

        const bool diag = (n >= 2 * m);    // last two tiles overlap the diagonal
        #pragma unroll
        for (int i = 0; i < 8; ++i) {
            int grow = m * BM + r0 + i;
            const float* bp = bias + ((size_t)bh * SEQ + grow) * SEQ + (size_t)n * BKT + c0;
            float4 b4 = *reinterpret_cast<const float4*>(bp);
            const float ba[4] = {b4.x, b4.y, b4.z, b4.w};
            #pragma unroll
            for (int j = 0; j < 4; ++j) {
                float s = sv[i][j] + ba[j];
                if (diag && (n * BKT + c0 + j > grow)) s = -INFINITY;
                sv[i][j] = s;
            }
        }

        // ---- online softmax (per row, reduce across 16 tx lanes) ----
        float corr[8];
        #pragma unroll
        for (int i = 0; i < 8; ++i) {
            float tmax = fmaxf(fmaxf(sv[i][0], sv[i][1]), fmaxf(sv[i][2], sv[i][3]));
            #pragma unroll
            for (int o = 1; o < 16; o <<= 1)
                tmax = fmaxf(tmax, __shfl_xor_sync(0xffffffffu, tmax, o));
            float mnew = fmaxf(mrow[i], tmax);
            corr[i] = __expf(mrow[i] - mnew);
            mrow[i] = mnew;

            float psum = 0.f;
            #pragma unroll
            for (int j = 0; j < 4; ++j) {
                float p = __expf(sv[i][j] - mnew);
                sv[i][j] = p;
                psum += p;
            }
            #pragma unroll
            for (int o = 1; o < 16; o <<= 1)
                psum += __shfl_xor_sync(0xffffffffu, psum, o);
            lrow[i] = lrow[i] * corr[i] + psum;
        }
        #pragma unroll
        for (int i = 0; i < 4; ++i) {
            u64 cc = pack2(corr[2 * i], corr[2 * i + 1]);
            #pragma unroll
            for (int j = 0; j < 4; ++j)
                acc2[i][j] = mul2(acc2[i][j], cc);
        }

        // ---- stash P transposed: Ps[c][r], packed float4 stores ----
        #pragma unroll
        for (int j = 0; j < 4; ++j) {
            float4 pa = make_float4(sv[0][j], sv[1][j], sv[2][j], sv[3][j]);
            float4 pb = make_float4(sv[4][j], sv[5][j], sv[6][j], sv[7][j]);
            *reinterpret_cast<float4*>(&Ps[(c0 + j) * SQ1 + r0])     = pa;
            *reinterpret_cast<float4*>(&Ps[(c0 + j) * SQ1 + r0 + 4]) = pb;
        }
        __syncthreads();

        // ---- O += P V (outer product over key index c) ----
        #pragma unroll 8
        for (int c = 0; c < BKT; ++c) {
            float4 pa = *reinterpret_cast<const float4*>(&Ps[c * SQ1 + r0]);
            float4 pb = *reinterpret_cast<const float4*>(&Ps[c * SQ1 + r0 + 4]);
            u64 pp[4] = { pack2(pa.x, pa.y), pack2(pa.z, pa.w),
                          pack2(pb.x, pb.y), pack2(pb.z, pb.w) };
            float4 vv = *reinterpret_cast<const float4*>(&Vs[c * SKV + c0]);
            u64 vd[4] = { dup2(vv.x), dup2(vv.y), dup2(vv.z), dup2(vv.w) };
            #pragma unroll
            for (int i = 0; i < 4; ++i)
                #pragma unroll
                for (int j = 0; j < 4; ++j)
                    fma2(acc2[i][j], pp[i], vd[j]);
        }
    }

    // ---- normalize + write ----
    #pragma unroll
    for (int i = 0; i < 4; ++i) {
        float inv_lo = 1.f / lrow[2 * i];
        float inv_hi = 1.f / lrow[2 * i + 1];
        float4 o_lo, o_hi;
        o_lo.x = lo2(acc2[i][0]) * inv_lo;
        o_lo.y = lo2(acc2[i][1]) * inv_lo;
        o_lo.z = lo2(acc2[i][2]) * inv_lo;
        o_lo.w = lo2(acc2[i][3]) * inv_lo;
        o_hi.x = hi2(acc2[i][0]) * inv_hi;
        o_hi.y = hi2(acc2[i][1]) * inv_hi;
        o_hi.z = hi2(acc2[i][2]) * inv_hi;
        o_hi.w = hi2(acc2[i][3]) * inv_hi;
        *reinterpret_cast<float4*>(op + (r0 + 2 * i)     * DD + c0) = o_lo;
        *reinterpret_cast<float4*>(op + (r0 + 2 * i + 1) * DD + c0) = o_hi;
    }
}

extern "C" void kernel_launch(void* const* d_in, const int* in_sizes, int n_in,
                              void* d_out, int out_size)
{
    const float* q    = (const float*)d_in[0];
    const float* k    = (const float*)d_in[1];
    const float* v    = (const float*)d_in[2];
    const float* bias = (const float*)d_in[3];
    float* out = (float*)d_out;

    const int smem_bytes = (DD * SQ1 + DD * SKV + BKT * SKV + BKT * SQ1) * (int)sizeof(float); // 102400
    cudaFuncSetAttribute(attn_fwd_kernel,
                         cudaFuncAttributeMaxDynamicSharedMemorySize, smem_bytes);

    dim3 grid(SEQ / BM, NBH);   // (8, 64)
    dim3 block(256);
    attn_fwd_kernel<<<grid, block, smem_bytes>>>(q, k, v, bias, out);
}

// round 5
// speedup vs baseline: 2.0035x; 1.8079x over previous
#include <cuda_runtime.h>
#include <math.h>
#include <stdint.h>

// Flash attention w/ bias + causal, fp32 I/O, tf32 mma.sync tensor cores.
// q,k,v: [B,H,N,D]; bias: [B,H,N,N]; out: [B,H,N,D]. B=4,H=16,N=1024,D=64.
// QK = 3x tf32 passes (hi/lo split), PV = 2x tf32 passes (V hi/lo, P rounded).

#define SEQ 1024
#define BM  128
#define BKT 64

// smem byte offsets; all tiles are 64-f32-wide rows (256B), XOR-swizzled
#define SM_QH 0u
#define SM_QL 32768u
#define SM_KH 65536u
#define SM_KL 81920u
#define SM_VH 98304u
#define SM_VL 114688u
#define SM_P  131072u           // 8 warps x 4KB (16 rows each)
#define SM_TOTAL 163840

static __device__ __forceinline__ uint32_t smem_u32(const void* p) {
    uint32_t a;
    asm("{ .reg .u64 t; cvta.to.shared.u64 t, %1; cvt.u32.u64 %0, t; }" : "=r"(a) : "l"(p));
    return a;
}
static __device__ __forceinline__ float rna_tf32(float x) {
    uint32_t u; asm("cvt.rna.tf32.f32 %0, %1;" : "=r"(u) : "f"(x));
    return __uint_as_float(u);
}
// tile address: row stride 256B, 16B chunks XOR-swizzled by row
static __device__ __forceinline__ uint32_t swz(int row, int chunk) {
    return (uint32_t)(row * 256 + ((chunk ^ (row & 7)) << 4));
}
// A fragment (16x8 tf32): m0=rows0-7/k0-3, m1=rows8-15/k0-3, m2=rows0-7/k4-7, m3=rows8-15/k4-7
static __device__ __forceinline__ void lda16(uint32_t a[4], uint32_t tb, int row0, int kk, int lane) {
    int sel = lane >> 3;
    int row = row0 + (lane & 7) + ((sel & 1) << 3);
    int ch  = kk * 2 + (sel >> 1);
    uint32_t addr = tb + swz(row, ch);
    asm volatile("ldmatrix.sync.aligned.m8n8.x4.shared.b16 {%0,%1,%2,%3}, [%4];"
                 : "=r"(a[0]), "=r"(a[1]), "=r"(a[2]), "=r"(a[3]) : "r"(addr));
}
// B fragments for TWO n-blocks (rows nrow0..+15 of an [n][k] row-major tile):
// m0/m1 = nblock0 kchunks, m2/m3 = nblock1 kchunks
static __device__ __forceinline__ void ldb16(uint32_t b[4], uint32_t tb, int nrow0, int kk, int lane) {
    int sel = lane >> 3;
    int row = nrow0 + ((sel >> 1) << 3) + (lane & 7);
    int ch  = kk * 2 + (sel & 1);
    uint32_t addr = tb + swz(row, ch);
    asm volatile("ldmatrix.sync.aligned.m8n8.x4.shared.b16 {%0,%1,%2,%3}, [%4];"
                 : "=r"(b[0]), "=r"(b[1]), "=r"(b[2]), "=r"(b[3]) : "r"(addr));
}
static __device__ __forceinline__ void mma8(float c[4], const uint32_t a[4], uint32_t b0, uint32_t b1) {
    asm volatile("mma.sync.aligned.m16n8k8.row.col.f32.tf32.tf32.f32 "
                 "{%0,%1,%2,%3}, {%4,%5,%6,%7}, {%8,%9}, {%0,%1,%2,%3};"
                 : "+f"(c[0]), "+f"(c[1]), "+f"(c[2]), "+f"(c[3])
                 : "r"(a[0]), "r"(a[1]), "r"(a[2]), "r"(a[3]), "r"(b0), "r"(b1));
}

__global__ __launch_bounds__(256, 1)
void attn_mma_kernel(const float* __restrict__ q,
                     const float* __restrict__ k,
                     const float* __restrict__ v,
                     const float* __restrict__ bias,
                     float* __restrict__ out)
{
    extern __shared__ char smem[];
    const uint32_t sb = smem_u32(smem);
    const int tid  = threadIdx.x;
    const int wid  = tid >> 5;
    const int lane = tid & 31;
    const int qd   = lane & 3;            // quad position (col pair selector)

    const int m  = 7 - (int)(blockIdx.x >> 6);   // heavy CTAs first
    const int bh = (int)(blockIdx.x & 63);

    // ---- prologue: stage Q (scaled, hi/lo split) ----
    const float* qp = q + ((size_t)bh * SEQ + (size_t)m * BM) * 64;
    #pragma unroll
    for (int i = 0; i < 8; ++i) {
        int lin = tid + i * 256;          // 2048 float4
        int row = lin >> 4;
        int ch  = lin & 15;
        float4 v4 = *reinterpret_cast<const float4*>(qp + row * 64 + ch * 4);
        float xs[4] = {v4.x * 0.125f, v4.y * 0.125f, v4.z * 0.125f, v4.w * 0.125f};
        float4 h4, l4;
        h4.x = rna_tf32(xs[0]); l4.x = rna_tf32(xs[0] - h4.x);
        h4.y = rna_tf32(xs[1]); l4.y = rna_tf32(xs[1] - h4.y);
        h4.z = rna_tf32(xs[2]); l4.z = rna_tf32(xs[2] - h4.z);
        h4.w = rna_tf32(xs[3]); l4.w = rna_tf32(xs[3] - h4.w);
        uint32_t o = swz(row, ch);
        *reinterpret_cast<float4*>(smem + SM_QH + o) = h4;
        *reinterpret_cast<float4*>(smem + SM_QL + o) = l4;
    }

    // this thread's two rows (within warp's 16-row band)
    const int wr0 = wid * 16;
    const int gra = m * BM + wr0 + (lane >> 2);       // row A global
    const int grb = gra + 8;                          // row B global

    float s[8][4];      // S accumulators: 8 n-blocks x (a0,a1 rowA | a2,a3 rowB)
    float o[8][4];      // O accumulators
    #pragma unroll
    for (int nb = 0; nb < 8; ++nb)
        #pragma unroll
        for (int e = 0; e < 4; ++e) o[nb][e] = 0.f;
    float m_a = -INFINITY, m_b = -INFINITY, l_a = 0.f, l_b = 0.f;

    const uint32_t pwarp = sb + SM_P + (uint32_t)wid * 4096u;
    const int ntiles = 2 * m + 2;
    const int wlast  = m * BM + wr0 + 15;

    for (int n = 0; n < ntiles; ++n) {
        __syncthreads();   // previous tile's K/V readers done

        // ---- stage K (hi/lo) and V transposed (hi/lo) ----
        const float* kp = k + ((size_t)bh * SEQ + (size_t)n * BKT) * 64;
        const float* vp = v + ((size_t)bh * SEQ + (size_t)n * BKT) * 64;
        #pragma unroll
        for (int i = 0; i < 4; ++i) {
            int lin = tid + i * 256;      // 1024 float4
            int row = lin >> 4;           // key index
            int ch  = lin & 15;
            float4 kv = *reinterpret_cast<const float4*>(kp + row * 64 + ch * 4);
            float4 h4, l4;
            h4.x = rna_tf32(kv.x); l4.x = rna_tf32(kv.x - h4.x);
            h4.y = rna_tf32(kv.y); l4.y = rna_tf32(kv.y - h4.y);
            h4.z = rna_tf32(kv.z); l4.z = rna_tf32(kv.z - h4.z);
            h4.w = rna_tf32(kv.w); l4.w = rna_tf32(kv.w - h4.w);
            uint32_t koff = swz(row, ch);
            *reinterpret_cast<float4*>(smem + SM_KH + koff) = h4;
            *reinterpret_cast<float4*>(smem + SM_KL + koff) = l4;

            float4 vv = *reinterpret_cast<const float4*>(vp + row * 64 + ch * 4);
            const float va[4] = {vv.x, vv.y, vv.z, vv.w};
            #pragma unroll
            for (int j = 0; j < 4; ++j) {
                float vh = rna_tf32(va[j]);
                float vl = rna_tf32(va[j] - vh);
                int dim = ch * 4 + j;
                uint32_t toff = swz(dim, row >> 2) + (uint32_t)((row & 3) * 4);
                *reinterpret_cast<float*>(smem + SM_VH + toff) = vh;
                *reinterpret_cast<float*>(smem + SM_VL + toff) = vl;
            }
        }
        __syncthreads();

        const bool active = (n * BKT <= wlast);
        if (active) {
            // bias prefetch (latency hides under the MMA block)
            float2 ba[8], bb[8];
            {
                const float* bpa = bias + ((size_t)bh * SEQ + gra) * SEQ + (size_t)n * BKT;
                const float* bpb = bias + ((size_t)bh * SEQ + grb) * SEQ + (size_t)n * BKT;
                #pragma unroll
                for (int nb = 0; nb < 8; ++nb) {
                    ba[nb] = *reinterpret_cast<const float2*>(bpa + nb * 8 + 2 * qd);
                    bb[nb] = *reinterpret_cast<const float2*>(bpb + nb * 8 + 2 * qd);
                }
            }

            // ---- S = Qh*Kh + Qh*Kl + Ql*Kh ----
            #pragma unroll
            for (int nb = 0; nb < 8; ++nb)
                #pragma unroll
                for (int e = 0; e < 4; ++e) s[nb][e] = 0.f;
            #pragma unroll
            for (int kk = 0; kk < 8; ++kk) {
                uint32_t aqh[4], aql[4];
                lda16(aqh, sb + SM_QH, wr0, kk, lane);
                lda16(aql, sb + SM_QL, wr0, kk, lane);
                #pragma unroll
                for (int nb2 = 0; nb2 < 4; ++nb2) {
                    uint32_t bhf[4], blf[4];
                    ldb16(bhf, sb + SM_KH, nb2 * 16, kk, lane);
                    ldb16(blf, sb + SM_KL, nb2 * 16, kk, lane);
                    mma8(s[2 * nb2],     aqh, bhf[0], bhf[1]);
                    mma8(s[2 * nb2 + 1], aqh, bhf[2], bhf[3]);
                    mma8(s[2 * nb2],     aqh, blf[0], blf[1]);
                    mma8(s[2 * nb2 + 1], aqh, blf[2], blf[3]);
                    mma8(s[2 * nb2],     aql, bhf[0], bhf[1]);
                    mma8(s[2 * nb2 + 1], aql, bhf[2], bhf[3]);
                }
            }

            // ---- bias + causal mask ----
            const int c00 = n * BKT + 2 * qd;
            #pragma unroll
            for (int nb = 0; nb < 8; ++nb) {
                int c0 = c00 + nb * 8, c1 = c0 + 1;
                s[nb][0] = (c0 <= gra) ? s[nb][0] + ba[nb].x : -INFINITY;
                s[nb][1] = (c1 <= gra) ? s[nb][1] + ba[nb].y : -INFINITY;
                s[nb][2] = (c0 <= grb) ? s[nb][2] + bb[nb].x : -INFINITY;
                s[nb][3] = (c1 <= grb) ? s[nb][3] + bb[nb].y : -INFINITY;
            }

            // ---- online softmax (rows shared by quad lanes) ----
            float tma = -INFINITY, tmb = -INFINITY;
            #pragma unroll
            for (int nb = 0; nb < 8; ++nb) {
                tma = fmaxf(tma, fmaxf(s[nb][0], s[nb][1]));
                tmb = fmaxf(tmb, fmaxf(s[nb][2], s[nb][3]));
            }
            tma = fmaxf(tma, __shfl_xor_sync(0xffffffffu, tma, 1));
            tma = fmaxf(tma, __shfl_xor_sync(0xffffffffu, tma, 2));
            tmb = fmaxf(tmb, __shfl_xor_sync(0xffffffffu, tmb, 1));
            tmb = fmaxf(tmb, __shfl_xor_sync(0xffffffffu, tmb, 2));

            float mna = fmaxf(m_a, tma), mnb = fmaxf(m_b, tmb);
            float ca = __expf(m_a - mna), cb = __expf(m_b - mnb);
            m_a = mna; m_b = mnb;

            float pa = 0.f, pb = 0.f;
            #pragma unroll
            for (int nb = 0; nb < 8; ++nb) {
                float p0 = rna_tf32(__expf(s[nb][0] - mna));
                float p1 = rna_tf32(__expf(s[nb][1] - mna));
                float p2 = rna_tf32(__expf(s[nb][2] - mnb));
                float p3 = rna_tf32(__expf(s[nb][3] - mnb));
                s[nb][0] = p0; s[nb][1] = p1; s[nb][2] = p2; s[nb][3] = p3;
                pa += p0 + p1; pb += p2 + p3;
            }
            pa += __shfl_xor_sync(0xffffffffu, pa, 1);
            pa += __shfl_xor_sync(0xffffffffu, pa, 2);
            pb += __shfl_xor_sync(0xffffffffu, pb, 1);
            pb += __shfl_xor_sync(0xffffffffu, pb, 2);
            l_a = l_a * ca + pa;
            l_b = l_b * cb + pb;
            #pragma unroll
            for (int nb = 0; nb < 8; ++nb) {
                o[nb][0] *= ca; o[nb][1] *= ca;
                o[nb][2] *= cb; o[nb][3] *= cb;
            }

            // ---- P -> warp-private smem ----
            const int lra = lane >> 2;
            #pragma unroll
            for (int nb = 0; nb < 8; ++nb) {
                int col = nb * 8 + 2 * qd;
                uint32_t off = swz(lra, col >> 2) + (uint32_t)((col & 3) * 4);
                *reinterpret_cast<float2*>(smem + SM_P + wid * 4096 + off) =
                    make_float2(s[nb][0], s[nb][1]);
                uint32_t off2 = swz(lra + 8, col >> 2) + (uint32_t)((col & 3) * 4);
                *reinterpret_cast<float2*>(smem + SM_P + wid * 4096 + off2) =
                    make_float2(s[nb][2], s[nb][3]);
            }
            __syncwarp();

            // ---- O += P*Vh + P*Vl ----
            #pragma unroll
            for (int kk = 0; kk < 8; ++kk) {
                uint32_t ap[4];
                lda16(ap, pwarp, 0, kk, lane);
                #pragma unroll
                for (int nb2 = 0; nb2 < 4; ++nb2) {
                    uint32_t bvh[4], bvl[4];
                    ldb16(bvh, sb + SM_VH, nb2 * 16, kk, lane);
                    ldb16(bvl, sb + SM_VL, nb2 * 16, kk, lane);
                    mma8(o[2 * nb2],     ap, bvh[0], bvh[1]);
                    mma8(o[2 * nb2 + 1], ap, bvh[2], bvh[3]);
                    mma8(o[2 * nb2],     ap, bvl[0], bvl[1]);
                    mma8(o[2 * nb2 + 1], ap, bvl[2], bvl[3]);
                }
            }
        }
    }

    // ---- epilogue ----
    const float ia = 1.f / l_a, ib = 1.f / l_b;
    float* opa = out + ((size_t)bh * SEQ + gra) * 64;
    float* opb = out + ((size_t)bh * SEQ + grb) * 64;
    #pragma unroll
    for (int nb = 0; nb < 8; ++nb) {
        int col = nb * 8 + 2 * qd;
        *reinterpret_cast<float2*>(opa + col) = make_float2(o[nb][0] * ia, o[nb][1] * ia);
        *reinterpret_cast<float2*>(opb + col) = make_float2(o[nb][2] * ib, o[nb][3] * ib);
    }
}

extern "C" void kernel_launch(void* const* d_in, const int* in_sizes, int n_in,
                              void* d_out, int out_size)
{
    const float* q    = (const float*)d_in[0];
    const float* k    = (const float*)d_in[1];
    const float* v    = (const float*)d_in[2];
    const float* bias = (const float*)d_in[3];
    float* out = (float*)d_out;

    cudaFuncSetAttribute(attn_mma_kernel,
                         cudaFuncAttributeMaxDynamicSharedMemorySize, SM_TOTAL);
    attn_mma_kernel<<<512, 256, SM_TOTAL>>>(q, k, v, bias, out);
}

// round 6
// speedup vs baseline: 2.6442x; 1.3198x over previous
#include <cuda_runtime.h>
#include <cuda_bf16.h>
#include <math.h>
#include <stdint.h>

// Flash attention w/ bias + causal, fp32 I/O, bf16 mma.sync (m16n8k16).
// q,k,v: [B,H,N,D]; bias: [B,H,N,N]; out: [B,H,N,D]. B=4,H=16,N=1024,D=64.
// QK = Qh*Kh + Qh*Kl + Ql*Kh ; PV = Ph*Vh + Ph*Vl + Pl*Vh  (bf16 hi/lo splits).

#define SEQ 1024
#define BM  128
#define BKT 64

// smem byte offsets; all tiles have 128B rows (64 bf16), XOR-swizzled 16B chunks
#define SM_QH 0u
#define SM_QL 16384u
#define SM_KH 32768u
#define SM_KL 40960u
#define SM_VH 49152u
#define SM_VL 57344u
#define SM_P  65536u            // 8 warps x 4KB (Ph 2KB + Pl 2KB)
#define SM_TOTAL 98304

static __device__ __forceinline__ uint32_t smem_u32(const void* p) {
    uint32_t a;
    asm("{ .reg .u64 t; cvta.to.shared.u64 t, %1; cvt.u32.u64 %0, t; }" : "=r"(a) : "l"(p));
    return a;
}
// row stride 128B, 16B chunks XOR-swizzled by row
static __device__ __forceinline__ uint32_t swz(int row, int chunk) {
    return (uint32_t)(row * 128 + ((chunk ^ (row & 7)) << 4));
}
static __device__ __forceinline__ void bsplit(float x, float& h, float& l) {
    __nv_bfloat16 hb = __float2bfloat16_rn(x);
    h = __bfloat162float(hb);
    l = x - h;
}
static __device__ __forceinline__ uint32_t bfpair(float a, float b) {
    __nv_bfloat162 t = __floats2bfloat162_rn(a, b);
    return *reinterpret_cast<uint32_t*>(&t);
}
static __device__ __forceinline__ void ldsm4(uint32_t r[4], uint32_t addr) {
    asm volatile("ldmatrix.sync.aligned.m8n8.x4.shared.b16 {%0,%1,%2,%3}, [%4];"
                 : "=r"(r[0]), "=r"(r[1]), "=r"(r[2]), "=r"(r[3]) : "r"(addr));
}
static __device__ __forceinline__ void ldsm4t(uint32_t r[4], uint32_t addr) {
    asm volatile("ldmatrix.sync.aligned.m8n8.x4.trans.shared.b16 {%0,%1,%2,%3}, [%4];"
                 : "=r"(r[0]), "=r"(r[1]), "=r"(r[2]), "=r"(r[3]) : "r"(addr));
}
// A fragment (m16 x k16 bf16), rows row0..row0+15, k-chunk kk (16 deep)
static __device__ __forceinline__ void lda(uint32_t a[4], uint32_t tb, int row0, int kk, int lane) {
    int sel = lane >> 3;
    int row = row0 + (lane & 7) + ((sel & 1) << 3);
    int ch  = kk * 2 + (sel >> 1);
    ldsm4(a, tb + swz(row, ch));
}
// B fragments for TWO n-blocks from row-major [n][k] tile (K): n0..n0+15, k-chunk kk
static __device__ __forceinline__ void ldb(uint32_t b[4], uint32_t tb, int n0, int kk, int lane) {
    int sel = lane >> 3;
    int row = n0 + ((sel >> 1) << 3) + (lane & 7);
    int ch  = kk * 2 + (sel & 1);
    ldsm4(b, tb + swz(row, ch));
}
// B fragments for TWO n-blocks from row-major [k][n] tile (V, trans load): k-chunk kk, n-block pair nb2
static __device__ __forceinline__ void ldbT(uint32_t b[4], uint32_t tb, int kk, int nb2, int lane) {
    int sel = lane >> 3;
    int row = kk * 16 + ((sel & 1) << 3) + (lane & 7);
    int ch  = nb2 * 2 + (sel >> 1);
    ldsm4t(b, tb + swz(row, ch));
}
static __device__ __forceinline__ void mmabf(float c[4], const uint32_t a[4], uint32_t b0, uint32_t b1) {
    asm volatile("mma.sync.aligned.m16n8k16.row.col.f32.bf16.bf16.f32 "
                 "{%0,%1,%2,%3}, {%4,%5,%6,%7}, {%8,%9}, {%0,%1,%2,%3};"
                 : "+f"(c[0]), "+f"(c[1]), "+f"(c[2]), "+f"(c[3])
                 : "r"(a[0]), "r"(a[1]), "r"(a[2]), "r"(a[3]), "r"(b0), "r"(b1));
}

__global__ __launch_bounds__(256, 1)
void attn_bf16_kernel(const float* __restrict__ q,
                      const float* __restrict__ k,
                      const float* __restrict__ v,
                      const float* __restrict__ bias,
                      float* __restrict__ out)
{
    extern __shared__ char smem[];
    const uint32_t sb = smem_u32(smem);
    const int tid  = threadIdx.x;
    const int wid  = tid >> 5;
    const int lane = tid & 31;
    const int qd   = lane & 3;

    const int m  = 7 - (int)(blockIdx.x >> 6);   // heavy CTAs first
    const int bh = (int)(blockIdx.x & 63);

    // ---- prologue: stage Q (scaled, bf16 hi/lo split) ----
    const float* qp = q + ((size_t)bh * SEQ + (size_t)m * BM) * 64;
    #pragma unroll
    for (int i = 0; i < 8; ++i) {
        int lin = tid + i * 256;
        int row = lin >> 4;
        int d4  = (lin & 15) * 4;
        float4 v4 = *reinterpret_cast<const float4*>(qp + row * 64 + d4);
        float h0, l0, h1, l1, h2, l2, h3, l3;
        bsplit(v4.x * 0.125f, h0, l0);
        bsplit(v4.y * 0.125f, h1, l1);
        bsplit(v4.z * 0.125f, h2, l2);
        bsplit(v4.w * 0.125f, h3, l3);
        uint32_t off = swz(row, d4 >> 3) + (uint32_t)((d4 & 7) * 2);
        *reinterpret_cast<uint2*>(smem + SM_QH + off) = make_uint2(bfpair(h0, h1), bfpair(h2, h3));
        *reinterpret_cast<uint2*>(smem + SM_QL + off) = make_uint2(bfpair(l0, l1), bfpair(l2, l3));
    }

    const int wr0 = wid * 16;
    const int gra = m * BM + wr0 + (lane >> 2);
    const int grb = gra + 8;

    float s[8][4];
    float o[8][4];
    #pragma unroll
    for (int nb = 0; nb < 8; ++nb)
        #pragma unroll
        for (int e = 0; e < 4; ++e) o[nb][e] = 0.f;
    float m_a = -INFINITY, m_b = -INFINITY, l_a = 0.f, l_b = 0.f;

    const uint32_t pwh = sb + SM_P + (uint32_t)wid * 4096u;
    const uint32_t pwl = pwh + 2048u;
    const int ntiles = 2 * m + 2;
    const int wlast  = m * BM + wr0 + 15;

    for (int n = 0; n < ntiles; ++n) {
        __syncthreads();

        // ---- stage K and V (both row-major [key][dim], bf16 hi/lo) ----
        const float* kp = k + ((size_t)bh * SEQ + (size_t)n * BKT) * 64;
        const float* vp = v + ((size_t)bh * SEQ + (size_t)n * BKT) * 64;
        #pragma unroll
        for (int i = 0; i < 4; ++i) {
            int lin = tid + i * 256;
            int row = lin >> 4;
            int d4  = (lin & 15) * 4;
            uint32_t off = swz(row, d4 >> 3) + (uint32_t)((d4 & 7) * 2);

            float4 kv = *reinterpret_cast<const float4*>(kp + row * 64 + d4);
            float h0, l0, h1, l1, h2, l2, h3, l3;
            bsplit(kv.x, h0, l0); bsplit(kv.y, h1, l1);
            bsplit(kv.z, h2, l2); bsplit(kv.w, h3, l3);
            *reinterpret_cast<uint2*>(smem + SM_KH + off) = make_uint2(bfpair(h0, h1), bfpair(h2, h3));
            *reinterpret_cast<uint2*>(smem + SM_KL + off) = make_uint2(bfpair(l0, l1), bfpair(l2, l3));

            float4 vv = *reinterpret_cast<const float4*>(vp + row * 64 + d4);
            bsplit(vv.x, h0, l0); bsplit(vv.y, h1, l1);
            bsplit(vv.z, h2, l2); bsplit(vv.w, h3, l3);
            *reinterpret_cast<uint2*>(smem + SM_VH + off) = make_uint2(bfpair(h0, h1), bfpair(h2, h3));
            *reinterpret_cast<uint2*>(smem + SM_VL + off) = make_uint2(bfpair(l0, l1), bfpair(l2, l3));
        }
        __syncthreads();

        const bool active = (n * BKT <= wlast);
        if (active) {
            // bias prefetch (LDG latency hides under the MMA block)
            float2 ba[8], bb[8];
            {
                const float* bpa = bias + ((size_t)bh * SEQ + gra) * SEQ + (size_t)n * BKT;
                const float* bpb = bias + ((size_t)bh * SEQ + grb) * SEQ + (size_t)n * BKT;
                #pragma unroll
                for (int nb = 0; nb < 8; ++nb) {
                    ba[nb] = *reinterpret_cast<const float2*>(bpa + nb * 8 + 2 * qd);
                    bb[nb] = *reinterpret_cast<const float2*>(bpb + nb * 8 + 2 * qd);
                }
            }

            // ---- S = Qh*Kh + Qh*Kl + Ql*Kh ----
            #pragma unroll
            for (int nb = 0; nb < 8; ++nb)
                #pragma unroll
                for (int e = 0; e < 4; ++e) s[nb][e] = 0.f;
            #pragma unroll
            for (int kk = 0; kk < 4; ++kk) {
                uint32_t aqh[4], aql[4];
                lda(aqh, sb + SM_QH, wr0, kk, lane);
                lda(aql, sb + SM_QL, wr0, kk, lane);
                #pragma unroll
                for (int nb2 = 0; nb2 < 4; ++nb2) {
                    uint32_t bhf[4], blf[4];
                    ldb(bhf, sb + SM_KH, nb2 * 16, kk, lane);
                    ldb(blf, sb + SM_KL, nb2 * 16, kk, lane);
                    mmabf(s[2 * nb2],     aqh, bhf[0], bhf[1]);
                    mmabf(s[2 * nb2 + 1], aqh, bhf[2], bhf[3]);
                    mmabf(s[2 * nb2],     aqh, blf[0], blf[1]);
                    mmabf(s[2 * nb2 + 1], aqh, blf[2], blf[3]);
                    mmabf(s[2 * nb2],     aql, bhf[0], bhf[1]);
                    mmabf(s[2 * nb2 + 1], aql, bhf[2], bhf[3]);
                }
            }

            // ---- bias + causal mask ----
            const int c00 = n * BKT + 2 * qd;
            #pragma unroll
            for (int nb = 0; nb < 8; ++nb) {
                int c0 = c00 + nb * 8, c1 = c0 + 1;
                s[nb][0] = (c0 <= gra) ? s[nb][0] + ba[nb].x : -INFINITY;
                s[nb][1] = (c1 <= gra) ? s[nb][1] + ba[nb].y : -INFINITY;
                s[nb][2] = (c0 <= grb) ? s[nb][2] + bb[nb].x : -INFINITY;
                s[nb][3] = (c1 <= grb) ? s[nb][3] + bb[nb].y : -INFINITY;
            }

            // ---- online softmax ----
            float tma = -INFINITY, tmb = -INFINITY;
            #pragma unroll
            for (int nb = 0; nb < 8; ++nb) {
                tma = fmaxf(tma, fmaxf(s[nb][0], s[nb][1]));
                tmb = fmaxf(tmb, fmaxf(s[nb][2], s[nb][3]));
            }
            tma = fmaxf(tma, __shfl_xor_sync(0xffffffffu, tma, 1));
            tma = fmaxf(tma, __shfl_xor_sync(0xffffffffu, tma, 2));
            tmb = fmaxf(tmb, __shfl_xor_sync(0xffffffffu, tmb, 1));
            tmb = fmaxf(tmb, __shfl_xor_sync(0xffffffffu, tmb, 2));

            float mna = fmaxf(m_a, tma), mnb = fmaxf(m_b, tmb);
            float ca = __expf(m_a - mna), cb = __expf(m_b - mnb);
            m_a = mna; m_b = mnb;

            float pa = 0.f, pb = 0.f;
            const int lra = lane >> 2;
            #pragma unroll
            for (int nb = 0; nb < 8; ++nb) {
                float p0 = __expf(s[nb][0] - mna);
                float p1 = __expf(s[nb][1] - mna);
                float p2 = __expf(s[nb][2] - mnb);
                float p3 = __expf(s[nb][3] - mnb);
                pa += p0 + p1; pb += p2 + p3;

                // store P hi/lo (bf16) to warp-private smem
                float h0, l0, h1, l1;
                uint32_t offA = swz(lra, nb) + (uint32_t)(4 * qd);
                bsplit(p0, h0, l0); bsplit(p1, h1, l1);
                *reinterpret_cast<uint32_t*>(smem + (pwh - sb) + offA) = bfpair(h0, h1);
                *reinterpret_cast<uint32_t*>(smem + (pwl - sb) + offA) = bfpair(l0, l1);
                uint32_t offB = swz(lra + 8, nb) + (uint32_t)(4 * qd);
                bsplit(p2, h0, l0); bsplit(p3, h1, l1);
                *reinterpret_cast<uint32_t*>(smem + (pwh - sb) + offB) = bfpair(h0, h1);
                *reinterpret_cast<uint32_t*>(smem + (pwl - sb) + offB) = bfpair(l0, l1);
            }
            pa += __shfl_xor_sync(0xffffffffu, pa, 1);
            pa += __shfl_xor_sync(0xffffffffu, pa, 2);
            pb += __shfl_xor_sync(0xffffffffu, pb, 1);
            pb += __shfl_xor_sync(0xffffffffu, pb, 2);
            l_a = l_a * ca + pa;
            l_b = l_b * cb + pb;
            #pragma unroll
            for (int nb = 0; nb < 8; ++nb) {
                o[nb][0] *= ca; o[nb][1] *= ca;
                o[nb][2] *= cb; o[nb][3] *= cb;
            }
            __syncwarp();

            // ---- O += Ph*Vh + Ph*Vl + Pl*Vh (V via trans ldmatrix) ----
            #pragma unroll
            for (int kk = 0; kk < 4; ++kk) {
                uint32_t aph[4], apl[4];
                lda(aph, pwh, 0, kk, lane);
                lda(apl, pwl, 0, kk, lane);
                #pragma unroll
                for (int nb2 = 0; nb2 < 4; ++nb2) {
                    uint32_t bvh[4], bvl[4];
                    ldbT(bvh, sb + SM_VH, kk, nb2, lane);
                    ldbT(bvl, sb + SM_VL, kk, nb2, lane);
                    mmabf(o[2 * nb2],     aph, bvh[0], bvh[1]);
                    mmabf(o[2 * nb2 + 1], aph, bvh[2], bvh[3]);
                    mmabf(o[2 * nb2],     aph, bvl[0], bvl[1]);
                    mmabf(o[2 * nb2 + 1], aph, bvl[2], bvl[3]);
                    mmabf(o[2 * nb2],     apl, bvh[0], bvh[1]);
                    mmabf(o[2 * nb2 + 1], apl, bvh[2], bvh[3]);
                }
            }
        }
    }

    // ---- epilogue ----
    const float ia = 1.f / l_a, ib = 1.f / l_b;
    float* opa = out + ((size_t)bh * SEQ + gra) * 64;
    float* opb = out + ((size_t)bh * SEQ + grb) * 64;
    #pragma unroll
    for (int nb = 0; nb < 8; ++nb) {
        int col = nb * 8 + 2 * qd;
        *reinterpret_cast<float2*>(opa + col) = make_float2(o[nb][0] * ia, o[nb][1] * ia);
        *reinterpret_cast<float2*>(opb + col) = make_float2(o[nb][2] * ib, o[nb][3] * ib);
    }
}

extern "C" void kernel_launch(void* const* d_in, const int* in_sizes, int n_in,
                              void* d_out, int out_size)
{
    const float* q    = (const float*)d_in[0];
    const float* k    = (const float*)d_in[1];
    const float* v    = (const float*)d_in[2];
    const float* bias = (const float*)d_in[3];
    float* out = (float*)d_out;

    cudaFuncSetAttribute(attn_bf16_kernel,
                         cudaFuncAttributeMaxDynamicSharedMemorySize, SM_TOTAL);
    attn_bf16_kernel<<<512, 256, SM_TOTAL>>>(q, k, v, bias, out);
}

// round 7
// speedup vs baseline: 2.6546x; 1.0039x over previous
#include <cuda_runtime.h>
#include <cuda_bf16.h>
#include <math.h>
#include <stdint.h>

// Flash attention w/ bias + causal, fp32 I/O, bf16 mma.sync (m16n8k16),
// software-pipelined: double-buffered K/V smem + register prefetch of next tile.
// QK = Qh*Kh + Qh*Kl + Ql*Kh ; PV = Ph*Vh + Ph*Vl + Pl*Vh.

#define SEQ 1024
#define BM  128
#define BKT 64

// smem layout (bytes): Q hi/lo, two K/V buffers, P
#define SM_QH 0u
#define SM_QL 16384u
#define SM_KV 32768u            // 2 buffers x 32768 (KH,KL,VH,VL each 8192)
#define KV_KH 0u
#define KV_KL 8192u
#define KV_VH 16384u
#define KV_VL 24576u
#define SM_P  98304u            // 8 warps x 4KB (Ph 2KB + Pl 2KB)
#define SM_TOTAL 131072

static __device__ __forceinline__ uint32_t smem_u32(const void* p) {
    uint32_t a;
    asm("{ .reg .u64 t; cvta.to.shared.u64 t, %1; cvt.u32.u64 %0, t; }" : "=r"(a) : "l"(p));
    return a;
}
// row stride 128B, 16B chunks XOR-swizzled by row
static __device__ __forceinline__ uint32_t swz(int row, int chunk) {
    return (uint32_t)(row * 128 + ((chunk ^ (row & 7)) << 4));
}
static __device__ __forceinline__ void bsplit(float x, float& h, float& l) {
    __nv_bfloat16 hb = __float2bfloat16_rn(x);
    h = __bfloat162float(hb);
    l = x - h;
}
static __device__ __forceinline__ uint32_t bfpair(float a, float b) {
    __nv_bfloat162 t = __floats2bfloat162_rn(a, b);
    return *reinterpret_cast<uint32_t*>(&t);
}
static __device__ __forceinline__ void ldsm4(uint32_t r[4], uint32_t addr) {
    asm volatile("ldmatrix.sync.aligned.m8n8.x4.shared.b16 {%0,%1,%2,%3}, [%4];"
                 : "=r"(r[0]), "=r"(r[1]), "=r"(r[2]), "=r"(r[3]) : "r"(addr));
}
static __device__ __forceinline__ void ldsm4t(uint32_t r[4], uint32_t addr) {
    asm volatile("ldmatrix.sync.aligned.m8n8.x4.trans.shared.b16 {%0,%1,%2,%3}, [%4];"
                 : "=r"(r[0]), "=r"(r[1]), "=r"(r[2]), "=r"(r[3]) : "r"(addr));
}
static __device__ __forceinline__ void lda(uint32_t a[4], uint32_t tb, int row0, int kk, int lane) {
    int sel = lane >> 3;
    int row = row0 + (lane & 7) + ((sel & 1) << 3);
    int ch  = kk * 2 + (sel >> 1);
    ldsm4(a, tb + swz(row, ch));
}
static __device__ __forceinline__ void ldb(uint32_t b[4], uint32_t tb, int n0, int kk, int lane) {
    int sel = lane >> 3;
    int row = n0 + ((sel >> 1) << 3) + (lane & 7);
    int ch  = kk * 2 + (sel & 1);
    ldsm4(b, tb + swz(row, ch));
}
static __device__ __forceinline__ void ldbT(uint32_t b[4], uint32_t tb, int kk, int nb2, int lane) {
    int sel = lane >> 3;
    int row = kk * 16 + ((sel & 1) << 3) + (lane & 7);
    int ch  = nb2 * 2 + (sel >> 1);
    ldsm4t(b, tb + swz(row, ch));
}
static __device__ __forceinline__ void mmabf(float c[4], const uint32_t a[4], uint32_t b0, uint32_t b1) {
    asm volatile("mma.sync.aligned.m16n8k16.row.col.f32.bf16.bf16.f32 "
                 "{%0,%1,%2,%3}, {%4,%5,%6,%7}, {%8,%9}, {%0,%1,%2,%3};"
                 : "+f"(c[0]), "+f"(c[1]), "+f"(c[2]), "+f"(c[3])
                 : "r"(a[0]), "r"(a[1]), "r"(a[2]), "r"(a[3]), "r"(b0), "r"(b1));
}

__global__ __launch_bounds__(256, 1)
void attn_bf16_kernel(const float* __restrict__ q,
                      const float* __restrict__ k,
                      const float* __restrict__ v,
                      const float* __restrict__ bias,
                      float* __restrict__ out)
{
    extern __shared__ char smem[];
    const uint32_t sb = smem_u32(smem);
    const int tid  = threadIdx.x;
    const int wid  = tid >> 5;
    const int lane = tid & 31;
    const int qd   = lane & 3;

    const int m  = 7 - (int)(blockIdx.x >> 6);   // heavy CTAs first
    const int bh = (int)(blockIdx.x & 63);

    // per-thread staging coords for K/V tiles (4 float4 each)
    const int srow[4] = { (tid + 0) >> 4, (tid + 256) >> 4, (tid + 512) >> 4, (tid + 768) >> 4 };
    const int sd4  = (tid & 15) * 4;
    const uint32_t soff[4] = {
        swz(srow[0], sd4 >> 3) + (uint32_t)((sd4 & 7) * 2),
        swz(srow[1], sd4 >> 3) + (uint32_t)((sd4 & 7) * 2),
        swz(srow[2], sd4 >> 3) + (uint32_t)((sd4 & 7) * 2),
        swz(srow[3], sd4 >> 3) + (uint32_t)((sd4 & 7) * 2)
    };

    // ---- prologue: stage Q (scaled, bf16 hi/lo split) ----
    const float* qp = q + ((size_t)bh * SEQ + (size_t)m * BM) * 64;
    #pragma unroll
    for (int i = 0; i < 8; ++i) {
        int lin = tid + i * 256;
        int row = lin >> 4;
        int d4  = (lin & 15) * 4;
        float4 v4 = *reinterpret_cast<const float4*>(qp + row * 64 + d4);
        float h0, l0, h1, l1, h2, l2, h3, l3;
        bsplit(v4.x * 0.125f, h0, l0);
        bsplit(v4.y * 0.125f, h1, l1);
        bsplit(v4.z * 0.125f, h2, l2);
        bsplit(v4.w * 0.125f, h3, l3);
        uint32_t off = swz(row, d4 >> 3) + (uint32_t)((d4 & 7) * 2);
        *reinterpret_cast<uint2*>(smem + SM_QH + off) = make_uint2(bfpair(h0, h1), bfpair(h2, h3));
        *reinterpret_cast<uint2*>(smem + SM_QL + off) = make_uint2(bfpair(l0, l1), bfpair(l2, l3));
    }

    const int wr0 = wid * 16;
    const int gra = m * BM + wr0 + (lane >> 2);
    const int grb = gra + 8;

    float s[8][4];
    float o[8][4];
    #pragma unroll
    for (int nb = 0; nb < 8; ++nb)
        #pragma unroll
        for (int e = 0; e < 4; ++e) o[nb][e] = 0.f;
    float m_a = -INFINITY, m_b = -INFINITY, l_a = 0.f, l_b = 0.f;

    const uint32_t pwh = sb + SM_P + (uint32_t)wid * 4096u;
    const uint32_t pwl = pwh + 2048u;
    const int ntiles = 2 * m + 2;
    const int wlast  = m * BM + wr0 + 15;

    const float* kbase = k + (size_t)bh * SEQ * 64;
    const float* vbase = v + (size_t)bh * SEQ * 64;

    // prefetch registers
    float4 kreg[4], vreg[4];
    #pragma unroll
    for (int i = 0; i < 4; ++i) {
        kreg[i] = *reinterpret_cast<const float4*>(kbase + srow[i] * 64 + sd4);
        vreg[i] = *reinterpret_cast<const float4*>(vbase + srow[i] * 64 + sd4);
    }
    // store tile 0 into buffer 0
    {
        char* kv0 = smem + SM_KV;
        #pragma unroll
        for (int i = 0; i < 4; ++i) {
            float h0, l0, h1, l1, h2, l2, h3, l3;
            bsplit(kreg[i].x, h0, l0); bsplit(kreg[i].y, h1, l1);
            bsplit(kreg[i].z, h2, l2); bsplit(kreg[i].w, h3, l3);
            *reinterpret_cast<uint2*>(kv0 + KV_KH + soff[i]) = make_uint2(bfpair(h0, h1), bfpair(h2, h3));
            *reinterpret_cast<uint2*>(kv0 + KV_KL + soff[i]) = make_uint2(bfpair(l0, l1), bfpair(l2, l3));
            bsplit(vreg[i].x, h0, l0); bsplit(vreg[i].y, h1, l1);
            bsplit(vreg[i].z, h2, l2); bsplit(vreg[i].w, h3, l3);
            *reinterpret_cast<uint2*>(kv0 + KV_VH + soff[i]) = make_uint2(bfpair(h0, h1), bfpair(h2, h3));
            *reinterpret_cast<uint2*>(kv0 + KV_VL + soff[i]) = make_uint2(bfpair(l0, l1), bfpair(l2, l3));
        }
    }

    for (int n = 0; n < ntiles; ++n) {
        // issue next tile's LDGs (drain under the MMAs below)
        const bool havenext = (n + 1 < ntiles);
        if (havenext) {
            const float* kp = kbase + (size_t)(n + 1) * BKT * 64;
            const float* vp = vbase + (size_t)(n + 1) * BKT * 64;
            #pragma unroll
            for (int i = 0; i < 4; ++i) {
                kreg[i] = *reinterpret_cast<const float4*>(kp + srow[i] * 64 + sd4);
                vreg[i] = *reinterpret_cast<const float4*>(vp + srow[i] * 64 + sd4);
            }
        }

        __syncthreads();   // current buffer's STS visible; prior reads of other buffer done

        const uint32_t kvb = SM_KV + (uint32_t)(n & 1) * 32768u;
        const uint32_t KH = sb + kvb + KV_KH;
        const uint32_t KL = sb + kvb + KV_KL;
        const uint32_t VH = sb + kvb + KV_VH;
        const uint32_t VL = sb + kvb + KV_VL;

        const bool active = (n * BKT <= wlast);
        if (active) {
            // bias prefetch (hides under QK MMAs)
            float2 ba[8], bb[8];
            {
                const float* bpa = bias + ((size_t)bh * SEQ + gra) * SEQ + (size_t)n * BKT;
                const float* bpb = bias + ((size_t)bh * SEQ + grb) * SEQ + (size_t)n * BKT;
                #pragma unroll
                for (int nb = 0; nb < 8; ++nb) {
                    ba[nb] = *reinterpret_cast<const float2*>(bpa + nb * 8 + 2 * qd);
                    bb[nb] = *reinterpret_cast<const float2*>(bpb + nb * 8 + 2 * qd);
                }
            }

            // ---- S = Qh*Kh + Qh*Kl + Ql*Kh ----
            #pragma unroll
            for (int nb = 0; nb < 8; ++nb)
                #pragma unroll
                for (int e = 0; e < 4; ++e) s[nb][e] = 0.f;
            #pragma unroll
            for (int kk = 0; kk < 4; ++kk) {
                uint32_t aqh[4], aql[4];
                lda(aqh, sb + SM_QH, wr0, kk, lane);
                lda(aql, sb + SM_QL, wr0, kk, lane);
                #pragma unroll
                for (int nb2 = 0; nb2 < 4; ++nb2) {
                    uint32_t bhf[4], blf[4];
                    ldb(bhf, KH, nb2 * 16, kk, lane);
                    ldb(blf, KL, nb2 * 16, kk, lane);
                    mmabf(s[2 * nb2],     aqh, bhf[0], bhf[1]);
                    mmabf(s[2 * nb2 + 1], aqh, bhf[2], bhf[3]);
                    mmabf(s[2 * nb2],     aqh, blf[0], blf[1]);
                    mmabf(s[2 * nb2 + 1], aqh, blf[2], blf[3]);
                    mmabf(s[2 * nb2],     aql, bhf[0], bhf[1]);
                    mmabf(s[2 * nb2 + 1], aql, bhf[2], bhf[3]);
                }
            }

            // ---- bias + causal mask ----
            const int c00 = n * BKT + 2 * qd;
            #pragma unroll
            for (int nb = 0; nb < 8; ++nb) {
                int c0 = c00 + nb * 8, c1 = c0 + 1;
                s[nb][0] = (c0 <= gra) ? s[nb][0] + ba[nb].x : -INFINITY;
                s[nb][1] = (c1 <= gra) ? s[nb][1] + ba[nb].y : -INFINITY;
                s[nb][2] = (c0 <= grb) ? s[nb][2] + bb[nb].x : -INFINITY;
                s[nb][3] = (c1 <= grb) ? s[nb][3] + bb[nb].y : -INFINITY;
            }

            // ---- online softmax ----
            float tma = -INFINITY, tmb = -INFINITY;
            #pragma unroll
            for (int nb = 0; nb < 8; ++nb) {
                tma = fmaxf(tma, fmaxf(s[nb][0], s[nb][1]));
                tmb = fmaxf(tmb, fmaxf(s[nb][2], s[nb][3]));
            }
            tma = fmaxf(tma, __shfl_xor_sync(0xffffffffu, tma, 1));
            tma = fmaxf(tma, __shfl_xor_sync(0xffffffffu, tma, 2));
            tmb = fmaxf(tmb, __shfl_xor_sync(0xffffffffu, tmb, 1));
            tmb = fmaxf(tmb, __shfl_xor_sync(0xffffffffu, tmb, 2));

            float mna = fmaxf(m_a, tma), mnb = fmaxf(m_b, tmb);
            float ca = __expf(m_a - mna), cb = __expf(m_b - mnb);
            m_a = mna; m_b = mnb;

            float pa = 0.f, pb = 0.f;
            const int lra = lane >> 2;
            #pragma unroll
            for (int nb = 0; nb < 8; ++nb) {
                float p0 = __expf(s[nb][0] - mna);
                float p1 = __expf(s[nb][1] - mna);
                float p2 = __expf(s[nb][2] - mnb);
                float p3 = __expf(s[nb][3] - mnb);
                pa += p0 + p1; pb += p2 + p3;

                float h0, l0, h1, l1;
                uint32_t offA = swz(lra, nb) + (uint32_t)(4 * qd);
                bsplit(p0, h0, l0); bsplit(p1, h1, l1);
                *reinterpret_cast<uint32_t*>(smem + (pwh - sb) + offA) = bfpair(h0, h1);
                *reinterpret_cast<uint32_t*>(smem + (pwl - sb) + offA) = bfpair(l0, l1);
                uint32_t offB = swz(lra + 8, nb) + (uint32_t)(4 * qd);
                bsplit(p2, h0, l0); bsplit(p3, h1, l1);
                *reinterpret_cast<uint32_t*>(smem + (pwh - sb) + offB) = bfpair(h0, h1);
                *reinterpret_cast<uint32_t*>(smem + (pwl - sb) + offB) = bfpair(l0, l1);
            }
            pa += __shfl_xor_sync(0xffffffffu, pa, 1);
            pa += __shfl_xor_sync(0xffffffffu, pa, 2);
            pb += __shfl_xor_sync(0xffffffffu, pb, 1);
            pb += __shfl_xor_sync(0xffffffffu, pb, 2);
            l_a = l_a * ca + pa;
            l_b = l_b * cb + pb;
            #pragma unroll
            for (int nb = 0; nb < 8; ++nb) {
                o[nb][0] *= ca; o[nb][1] *= ca;
                o[nb][2] *= cb; o[nb][3] *= cb;
            }
            __syncwarp();
        }

        // ---- split + store NEXT tile into the other buffer (issues ahead of PV MMAs) ----
        if (havenext) {
            char* kvn = smem + SM_KV + (size_t)((n + 1) & 1) * 32768u;
            #pragma unroll
            for (int i = 0; i < 4; ++i) {
                float h0, l0, h1, l1, h2, l2, h3, l3;
                bsplit(kreg[i].x, h0, l0); bsplit(kreg[i].y, h1, l1);
                bsplit(kreg[i].z, h2, l2); bsplit(kreg[i].w, h3, l3);
                *reinterpret_cast<uint2*>(kvn + KV_KH + soff[i]) = make_uint2(bfpair(h0, h1), bfpair(h2, h3));
                *reinterpret_cast<uint2*>(kvn + KV_KL + soff[i]) = make_uint2(bfpair(l0, l1), bfpair(l2, l3));
                bsplit(vreg[i].x, h0, l0); bsplit(vreg[i].y, h1, l1);
                bsplit(vreg[i].z, h2, l2); bsplit(vreg[i].w, h3, l3);
                *reinterpret_cast<uint2*>(kvn + KV_VH + soff[i]) = make_uint2(bfpair(h0, h1), bfpair(h2, h3));
                *reinterpret_cast<uint2*>(kvn + KV_VL + soff[i]) = make_uint2(bfpair(l0, l1), bfpair(l2, l3));
            }
        }

        if (active) {
            // ---- O += Ph*Vh + Ph*Vl + Pl*Vh ----
            #pragma unroll
            for (int kk = 0; kk < 4; ++kk) {
                uint32_t aph[4], apl[4];
                lda(aph, pwh, 0, kk, lane);
                lda(apl, pwl, 0, kk, lane);
                #pragma unroll
                for (int nb2 = 0; nb2 < 4; ++nb2) {
                    uint32_t bvh[4], bvl[4];
                    ldbT(bvh, VH, kk, nb2, lane);
                    ldbT(bvl, VL, kk, nb2, lane);
                    mmabf(o[2 * nb2],     aph, bvh[0], bvh[1]);
                    mmabf(o[2 * nb2 + 1], aph, bvh[2], bvh[3]);
                    mmabf(o[2 * nb2],     aph, bvl[0], bvl[1]);
                    mmabf(o[2 * nb2 + 1], aph, bvl[2], bvl[3]);
                    mmabf(o[2 * nb2],     apl, bvh[0], bvh[1]);
                    mmabf(o[2 * nb2 + 1], apl, bvh[2], bvh[3]);
                }
            }
        }
    }

    // ---- epilogue ----
    const float ia = 1.f / l_a, ib = 1.f / l_b;
    float* opa = out + ((size_t)bh * SEQ + gra) * 64;
    float* opb = out + ((size_t)bh * SEQ + grb) * 64;
    #pragma unroll
    for (int nb = 0; nb < 8; ++nb) {
        int col = nb * 8 + 2 * qd;
        *reinterpret_cast<float2*>(opa + col) = make_float2(o[nb][0] * ia, o[nb][1] * ia);
        *reinterpret_cast<float2*>(opb + col) = make_float2(o[nb][2] * ib, o[nb][3] * ib);
    }
}

extern "C" void kernel_launch(void* const* d_in, const int* in_sizes, int n_in,
                              void* d_out, int out_size)
{
    const float* q    = (const float*)d_in[0];
    const float* k    = (const float*)d_in[1];
    const float* v    = (const float*)d_in[2];
    const float* bias = (const float*)d_in[3];
    float* out = (float*)d_out;

    cudaFuncSetAttribute(attn_bf16_kernel,
                         cudaFuncAttributeMaxDynamicSharedMemorySize, SM_TOTAL);
    attn_bf16_kernel<<<512, 256, SM_TOTAL>>>(q, k, v, bias, out);
}

// round 8
// speedup vs baseline: 3.4151x; 1.2865x over previous
#include <cuda_runtime.h>
#include <cuda_bf16.h>
#include <math.h>
#include <stdint.h>

// Flash attention w/ bias + causal, fp32 I/O, bf16 mma.sync (m16n8k16).
// 2 CTAs/SM (96KB smem, 128-reg cap) for latency hiding.
// QK = Qh*Kh + Qh*Kl + Ql*Kh ; PV = Ph*Vh + Ph*Vl + Pl*Vh.

#define SEQ 1024
#define BM  128
#define BKT 64

// smem byte offsets; all tiles have 128B rows (64 bf16), XOR-swizzled 16B chunks
#define SM_QH 0u
#define SM_QL 16384u
#define SM_KH 32768u
#define SM_KL 40960u
#define SM_VH 49152u
#define SM_VL 57344u
#define SM_P  65536u            // 8 warps x 4KB (Ph 2KB + Pl 2KB)
#define SM_TOTAL 98304

static __device__ __forceinline__ uint32_t smem_u32(const void* p) {
    uint32_t a;
    asm("{ .reg .u64 t; cvta.to.shared.u64 t, %1; cvt.u32.u64 %0, t; }" : "=r"(a) : "l"(p));
    return a;
}
static __device__ __forceinline__ uint32_t swz(int row, int chunk) {
    return (uint32_t)(row * 128 + ((chunk ^ (row & 7)) << 4));
}
static __device__ __forceinline__ void bsplit(float x, float& h, float& l) {
    __nv_bfloat16 hb = __float2bfloat16_rn(x);
    h = __bfloat162float(hb);
    l = x - h;
}
static __device__ __forceinline__ uint32_t bfpair(float a, float b) {
    __nv_bfloat162 t = __floats2bfloat162_rn(a, b);
    return *reinterpret_cast<uint32_t*>(&t);
}
static __device__ __forceinline__ void ldsm4(uint32_t r[4], uint32_t addr) {
    asm volatile("ldmatrix.sync.aligned.m8n8.x4.shared.b16 {%0,%1,%2,%3}, [%4];"
                 : "=r"(r[0]), "=r"(r[1]), "=r"(r[2]), "=r"(r[3]) : "r"(addr));
}
static __device__ __forceinline__ void ldsm4t(uint32_t r[4], uint32_t addr) {
    asm volatile("ldmatrix.sync.aligned.m8n8.x4.trans.shared.b16 {%0,%1,%2,%3}, [%4];"
                 : "=r"(r[0]), "=r"(r[1]), "=r"(r[2]), "=r"(r[3]) : "r"(addr));
}
static __device__ __forceinline__ void lda(uint32_t a[4], uint32_t tb, int row0, int kk, int lane) {
    int sel = lane >> 3;
    int row = row0 + (lane & 7) + ((sel & 1) << 3);
    int ch  = kk * 2 + (sel >> 1);
    ldsm4(a, tb + swz(row, ch));
}
static __device__ __forceinline__ void ldb(uint32_t b[4], uint32_t tb, int n0, int kk, int lane) {
    int sel = lane >> 3;
    int row = n0 + ((sel >> 1) << 3) + (lane & 7);
    int ch  = kk * 2 + (sel & 1);
    ldsm4(b, tb + swz(row, ch));
}
static __device__ __forceinline__ void ldbT(uint32_t b[4], uint32_t tb, int kk, int nb2, int lane) {
    int sel = lane >> 3;
    int row = kk * 16 + ((sel & 1) << 3) + (lane & 7);
    int ch  = nb2 * 2 + (sel >> 1);
    ldsm4t(b, tb + swz(row, ch));
}
static __device__ __forceinline__ void mmabf(float c[4], const uint32_t a[4], uint32_t b0, uint32_t b1) {
    asm volatile("mma.sync.aligned.m16n8k16.row.col.f32.bf16.bf16.f32 "
                 "{%0,%1,%2,%3}, {%4,%5,%6,%7}, {%8,%9}, {%0,%1,%2,%3};"
                 : "+f"(c[0]), "+f"(c[1]), "+f"(c[2]), "+f"(c[3])
                 : "r"(a[0]), "r"(a[1]), "r"(a[2]), "r"(a[3]), "r"(b0), "r"(b1));
}

__global__ __launch_bounds__(256, 2)
void attn_bf16_kernel(const float* __restrict__ q,
                      const float* __restrict__ k,
                      const float* __restrict__ v,
                      const float* __restrict__ bias,
                      float* __restrict__ out)
{
    extern __shared__ char smem[];
    const uint32_t sb = smem_u32(smem);
    const int tid  = threadIdx.x;
    const int wid  = tid >> 5;
    const int lane = tid & 31;
    const int qd   = lane & 3;

    const int m  = 7 - (int)(blockIdx.x >> 6);   // heavy CTAs first
    const int bh = (int)(blockIdx.x & 63);

    // ---- prologue: stage Q (scaled, bf16 hi/lo split) ----
    const float* qp = q + ((size_t)bh * SEQ + (size_t)m * BM) * 64;
    #pragma unroll
    for (int i = 0; i < 8; ++i) {
        int lin = tid + i * 256;
        int row = lin >> 4;
        int d4  = (lin & 15) * 4;
        float4 v4 = *reinterpret_cast<const float4*>(qp + row * 64 + d4);
        float h0, l0, h1, l1, h2, l2, h3, l3;
        bsplit(v4.x * 0.125f, h0, l0);
        bsplit(v4.y * 0.125f, h1, l1);
        bsplit(v4.z * 0.125f, h2, l2);
        bsplit(v4.w * 0.125f, h3, l3);
        uint32_t off = swz(row, d4 >> 3) + (uint32_t)((d4 & 7) * 2);
        *reinterpret_cast<uint2*>(smem + SM_QH + off) = make_uint2(bfpair(h0, h1), bfpair(h2, h3));
        *reinterpret_cast<uint2*>(smem + SM_QL + off) = make_uint2(bfpair(l0, l1), bfpair(l2, l3));
    }

    const int wr0 = wid * 16;
    const int gra = m * BM + wr0 + (lane >> 2);
    const int grb = gra + 8;

    float s[8][4];
    float o[8][4];
    #pragma unroll
    for (int nb = 0; nb < 8; ++nb)
        #pragma unroll
        for (int e = 0; e < 4; ++e) o[nb][e] = 0.f;
    float m_a = -INFINITY, m_b = -INFINITY, l_a = 0.f, l_b = 0.f;

    const uint32_t pwh = sb + SM_P + (uint32_t)wid * 4096u;
    const uint32_t pwl = pwh + 2048u;
    const int ntiles = 2 * m + 2;
    const int wlast  = m * BM + wr0 + 15;

    for (int n = 0; n < ntiles; ++n) {
        __syncthreads();

        // ---- stage K and V (row-major [key][dim], bf16 hi/lo) ----
        const float* kp = k + ((size_t)bh * SEQ + (size_t)n * BKT) * 64;
        const float* vp = v + ((size_t)bh * SEQ + (size_t)n * BKT) * 64;
        #pragma unroll
        for (int i = 0; i < 4; ++i) {
            int lin = tid + i * 256;
            int row = lin >> 4;
            int d4  = (lin & 15) * 4;
            uint32_t off = swz(row, d4 >> 3) + (uint32_t)((d4 & 7) * 2);

            float4 kv = *reinterpret_cast<const float4*>(kp + row * 64 + d4);
            float h0, l0, h1, l1, h2, l2, h3, l3;
            bsplit(kv.x, h0, l0); bsplit(kv.y, h1, l1);
            bsplit(kv.z, h2, l2); bsplit(kv.w, h3, l3);
            *reinterpret_cast<uint2*>(smem + SM_KH + off) = make_uint2(bfpair(h0, h1), bfpair(h2, h3));
            *reinterpret_cast<uint2*>(smem + SM_KL + off) = make_uint2(bfpair(l0, l1), bfpair(l2, l3));

            float4 vv = *reinterpret_cast<const float4*>(vp + row * 64 + d4);
            bsplit(vv.x, h0, l0); bsplit(vv.y, h1, l1);
            bsplit(vv.z, h2, l2); bsplit(vv.w, h3, l3);
            *reinterpret_cast<uint2*>(smem + SM_VH + off) = make_uint2(bfpair(h0, h1), bfpair(h2, h3));
            *reinterpret_cast<uint2*>(smem + SM_VL + off) = make_uint2(bfpair(l0, l1), bfpair(l2, l3));
        }
        __syncthreads();

        const bool active = (n * BKT <= wlast);
        if (active) {
            // bias prefetch (hides under QK MMAs; ptxas may sink under reg cap)
            float2 ba[8], bb[8];
            {
                const float* bpa = bias + ((size_t)bh * SEQ + gra) * SEQ + (size_t)n * BKT;
                const float* bpb = bias + ((size_t)bh * SEQ + grb) * SEQ + (size_t)n * BKT;
                #pragma unroll
                for (int nb = 0; nb < 8; ++nb) {
                    ba[nb] = *reinterpret_cast<const float2*>(bpa + nb * 8 + 2 * qd);
                    bb[nb] = *reinterpret_cast<const float2*>(bpb + nb * 8 + 2 * qd);
                }
            }

            // ---- S = Qh*Kh + Qh*Kl + Ql*Kh ----
            #pragma unroll
            for (int nb = 0; nb < 8; ++nb)
                #pragma unroll
                for (int e = 0; e < 4; ++e) s[nb][e] = 0.f;
            #pragma unroll
            for (int kk = 0; kk < 4; ++kk) {
                uint32_t aqh[4], aql[4];
                lda(aqh, sb + SM_QH, wr0, kk, lane);
                lda(aql, sb + SM_QL, wr0, kk, lane);
                #pragma unroll
                for (int nb2 = 0; nb2 < 4; ++nb2) {
                    uint32_t bhf[4], blf[4];
                    ldb(bhf, sb + SM_KH, nb2 * 16, kk, lane);
                    ldb(blf, sb + SM_KL, nb2 * 16, kk, lane);
                    mmabf(s[2 * nb2],     aqh, bhf[0], bhf[1]);
                    mmabf(s[2 * nb2 + 1], aqh, bhf[2], bhf[3]);
                    mmabf(s[2 * nb2],     aqh, blf[0], blf[1]);
                    mmabf(s[2 * nb2 + 1], aqh, blf[2], blf[3]);
                    mmabf(s[2 * nb2],     aql, bhf[0], bhf[1]);
                    mmabf(s[2 * nb2 + 1], aql, bhf[2], bhf[3]);
                }
            }

            // ---- bias + causal mask ----
            const int c00 = n * BKT + 2 * qd;
            #pragma unroll
            for (int nb = 0; nb < 8; ++nb) {
                int c0 = c00 + nb * 8, c1 = c0 + 1;
                s[nb][0] = (c0 <= gra) ? s[nb][0] + ba[nb].x : -INFINITY;
                s[nb][1] = (c1 <= gra) ? s[nb][1] + ba[nb].y : -INFINITY;
                s[nb][2] = (c0 <= grb) ? s[nb][2] + bb[nb].x : -INFINITY;
                s[nb][3] = (c1 <= grb) ? s[nb][3] + bb[nb].y : -INFINITY;
            }

            // ---- online softmax ----
            float tma = -INFINITY, tmb = -INFINITY;
            #pragma unroll
            for (int nb = 0; nb < 8; ++nb) {
                tma = fmaxf(tma, fmaxf(s[nb][0], s[nb][1]));
                tmb = fmaxf(tmb, fmaxf(s[nb][2], s[nb][3]));
            }
            tma = fmaxf(tma, __shfl_xor_sync(0xffffffffu, tma, 1));
            tma = fmaxf(tma, __shfl_xor_sync(0xffffffffu, tma, 2));
            tmb = fmaxf(tmb, __shfl_xor_sync(0xffffffffu, tmb, 1));
            tmb = fmaxf(tmb, __shfl_xor_sync(0xffffffffu, tmb, 2));

            float mna = fmaxf(m_a, tma), mnb = fmaxf(m_b, tmb);
            float ca = __expf(m_a - mna), cb = __expf(m_b - mnb);
            m_a = mna; m_b = mnb;

            float pa = 0.f, pb = 0.f;
            const int lra = lane >> 2;
            #pragma unroll
            for (int nb = 0; nb < 8; ++nb) {
                float p0 = __expf(s[nb][0] - mna);
                float p1 = __expf(s[nb][1] - mna);
                float p2 = __expf(s[nb][2] - mnb);
                float p3 = __expf(s[nb][3] - mnb);
                pa += p0 + p1; pb += p2 + p3;

                float h0, l0, h1, l1;
                uint32_t offA = swz(lra, nb) + (uint32_t)(4 * qd);
                bsplit(p0, h0, l0); bsplit(p1, h1, l1);
                *reinterpret_cast<uint32_t*>(smem + (pwh - sb) + offA) = bfpair(h0, h1);
                *reinterpret_cast<uint32_t*>(smem + (pwl - sb) + offA) = bfpair(l0, l1);
                uint32_t offB = swz(lra + 8, nb) + (uint32_t)(4 * qd);
                bsplit(p2, h0, l0); bsplit(p3, h1, l1);
                *reinterpret_cast<uint32_t*>(smem + (pwh - sb) + offB) = bfpair(h0, h1);
                *reinterpret_cast<uint32_t*>(smem + (pwl - sb) + offB) = bfpair(l0, l1);
            }
            pa += __shfl_xor_sync(0xffffffffu, pa, 1);
            pa += __shfl_xor_sync(0xffffffffu, pa, 2);
            pb += __shfl_xor_sync(0xffffffffu, pb, 1);
            pb += __shfl_xor_sync(0xffffffffu, pb, 2);
            l_a = l_a * ca + pa;
            l_b = l_b * cb + pb;
            #pragma unroll
            for (int nb = 0; nb < 8; ++nb) {
                o[nb][0] *= ca; o[nb][1] *= ca;
                o[nb][2] *= cb; o[nb][3] *= cb;
            }
            __syncwarp();

            // ---- O += Ph*Vh + Ph*Vl + Pl*Vh (V via trans ldmatrix) ----
            #pragma unroll
            for (int kk = 0; kk < 4; ++kk) {
                uint32_t aph[4], apl[4];
                lda(aph, pwh, 0, kk, lane);
                lda(apl, pwl, 0, kk, lane);
                #pragma unroll
                for (int nb2 = 0; nb2 < 4; ++nb2) {
                    uint32_t bvh[4], bvl[4];
                    ldbT(bvh, sb + SM_VH, kk, nb2, lane);
                    ldbT(bvl, sb + SM_VL, kk, nb2, lane);
                    mmabf(o[2 * nb2],     aph, bvh[0], bvh[1]);
                    mmabf(o[2 * nb2 + 1], aph, bvh[2], bvh[3]);
                    mmabf(o[2 * nb2],     aph, bvl[0], bvl[1]);
                    mmabf(o[2 * nb2 + 1], aph, bvl[2], bvl[3]);
                    mmabf(o[2 * nb2],     apl, bvh[0], bvh[1]);
                    mmabf(o[2 * nb2 + 1], apl, bvh[2], bvh[3]);
                }
            }
        }
    }

    // ---- epilogue ----
    const float ia = 1.f / l_a, ib = 1.f / l_b;
    float* opa = out + ((size_t)bh * SEQ + gra) * 64;
    float* opb = out + ((size_t)bh * SEQ + grb) * 64;
    #pragma unroll
    for (int nb = 0; nb < 8; ++nb) {
        int col = nb * 8 + 2 * qd;
        *reinterpret_cast<float2*>(opa + col) = make_float2(o[nb][0] * ia, o[nb][1] * ia);
        *reinterpret_cast<float2*>(opb + col) = make_float2(o[nb][2] * ib, o[nb][3] * ib);
    }
}

extern "C" void kernel_launch(void* const* d_in, const int* in_sizes, int n_in,
                              void* d_out, int out_size)
{
    const float* q    = (const float*)d_in[0];
    const float* k    = (const float*)d_in[1];
    const float* v    = (const float*)d_in[2];
    const float* bias = (const float*)d_in[3];
    float* out = (float*)d_out;

    cudaFuncSetAttribute(attn_bf16_kernel,
                         cudaFuncAttributeMaxDynamicSharedMemorySize, SM_TOTAL);
    attn_bf16_kernel<<<512, 256, SM_TOTAL>>>(q, k, v, bias, out);
}

// round 9
// speedup vs baseline: 3.6307x; 1.0631x over previous
#include <cuda_runtime.h>
#include <cuda_bf16.h>
#include <math.h>
#include <stdint.h>

// Flash attention w/ bias + causal, fp32 I/O, bf16 mma.sync (m16n8k16).
// 2 CTAs/SM (64KB smem, 128-reg cap). P fed to PV MMA directly from
// S-accumulator registers (C-fragment == A-fragment layout); no P smem.
// QK = Qh*Kh + Qh*Kl + Ql*Kh ; PV = Ph*Vh + Ph*Vl + Pl*Vh.

#define SEQ 1024
#define BM  128
#define BKT 64

// smem byte offsets; all tiles have 128B rows (64 bf16), XOR-swizzled 16B chunks
#define SM_QH 0u
#define SM_QL 16384u
#define SM_KH 32768u
#define SM_KL 40960u
#define SM_VH 49152u
#define SM_VL 57344u
#define SM_TOTAL 65536

static __device__ __forceinline__ uint32_t smem_u32(const void* p) {
    uint32_t a;
    asm("{ .reg .u64 t; cvta.to.shared.u64 t, %1; cvt.u32.u64 %0, t; }" : "=r"(a) : "l"(p));
    return a;
}
static __device__ __forceinline__ uint32_t swz(int row, int chunk) {
    return (uint32_t)(row * 128 + ((chunk ^ (row & 7)) << 4));
}
static __device__ __forceinline__ void bsplit(float x, float& h, float& l) {
    __nv_bfloat16 hb = __float2bfloat16_rn(x);
    h = __bfloat162float(hb);
    l = x - h;
}
static __device__ __forceinline__ uint32_t bfpair(float a, float b) {
    __nv_bfloat162 t = __floats2bfloat162_rn(a, b);
    return *reinterpret_cast<uint32_t*>(&t);
}
static __device__ __forceinline__ void ldsm4(uint32_t r[4], uint32_t addr) {
    asm volatile("ldmatrix.sync.aligned.m8n8.x4.shared.b16 {%0,%1,%2,%3}, [%4];"
                 : "=r"(r[0]), "=r"(r[1]), "=r"(r[2]), "=r"(r[3]) : "r"(addr));
}
static __device__ __forceinline__ void ldsm4t(uint32_t r[4], uint32_t addr) {
    asm volatile("ldmatrix.sync.aligned.m8n8.x4.trans.shared.b16 {%0,%1,%2,%3}, [%4];"
                 : "=r"(r[0]), "=r"(r[1]), "=r"(r[2]), "=r"(r[3]) : "r"(addr));
}
static __device__ __forceinline__ void lda(uint32_t a[4], uint32_t tb, int row0, int kk, int lane) {
    int sel = lane >> 3;
    int row = row0 + (lane & 7) + ((sel & 1) << 3);
    int ch  = kk * 2 + (sel >> 1);
    ldsm4(a, tb + swz(row, ch));
}
static __device__ __forceinline__ void ldb(uint32_t b[4], uint32_t tb, int n0, int kk, int lane) {
    int sel = lane >> 3;
    int row = n0 + ((sel >> 1) << 3) + (lane & 7);
    int ch  = kk * 2 + (sel & 1);
    ldsm4(b, tb + swz(row, ch));
}
static __device__ __forceinline__ void ldbT(uint32_t b[4], uint32_t tb, int kk, int nb2, int lane) {
    int sel = lane >> 3;
    int row = kk * 16 + ((sel & 1) << 3) + (lane & 7);
    int ch  = nb2 * 2 + (sel >> 1);
    ldsm4t(b, tb + swz(row, ch));
}
static __device__ __forceinline__ void mmabf(float c[4], const uint32_t a[4], uint32_t b0, uint32_t b1) {
    asm volatile("mma.sync.aligned.m16n8k16.row.col.f32.bf16.bf16.f32 "
                 "{%0,%1,%2,%3}, {%4,%5,%6,%7}, {%8,%9}, {%0,%1,%2,%3};"
                 : "+f"(c[0]), "+f"(c[1]), "+f"(c[2]), "+f"(c[3])
                 : "r"(a[0]), "r"(a[1]), "r"(a[2]), "r"(a[3]), "r"(b0), "r"(b1));
}

__global__ __launch_bounds__(256, 2)
void attn_bf16_kernel(const float* __restrict__ q,
                      const float* __restrict__ k,
                      const float* __restrict__ v,
                      const float* __restrict__ bias,
                      float* __restrict__ out)
{
    extern __shared__ char smem[];
    const uint32_t sb = smem_u32(smem);
    const int tid  = threadIdx.x;
    const int wid  = tid >> 5;
    const int lane = tid & 31;
    const int qd   = lane & 3;

    const int m  = 7 - (int)(blockIdx.x >> 6);   // heavy CTAs first
    const int bh = (int)(blockIdx.x & 63);

    // ---- prologue: stage Q (scaled, bf16 hi/lo split) ----
    const float* qp = q + ((size_t)bh * SEQ + (size_t)m * BM) * 64;
    #pragma unroll
    for (int i = 0; i < 8; ++i) {
        int lin = tid + i * 256;
        int row = lin >> 4;
        int d4  = (lin & 15) * 4;
        float4 v4 = *reinterpret_cast<const float4*>(qp + row * 64 + d4);
        float h0, l0, h1, l1, h2, l2, h3, l3;
        bsplit(v4.x * 0.125f, h0, l0);
        bsplit(v4.y * 0.125f, h1, l1);
        bsplit(v4.z * 0.125f, h2, l2);
        bsplit(v4.w * 0.125f, h3, l3);
        uint32_t off = swz(row, d4 >> 3) + (uint32_t)((d4 & 7) * 2);
        *reinterpret_cast<uint2*>(smem + SM_QH + off) = make_uint2(bfpair(h0, h1), bfpair(h2, h3));
        *reinterpret_cast<uint2*>(smem + SM_QL + off) = make_uint2(bfpair(l0, l1), bfpair(l2, l3));
    }

    const int wr0 = wid * 16;
    const int gra = m * BM + wr0 + (lane >> 2);
    const int grb = gra + 8;

    float s[8][4];
    float o[8][4];
    #pragma unroll
    for (int nb = 0; nb < 8; ++nb)
        #pragma unroll
        for (int e = 0; e < 4; ++e) o[nb][e] = 0.f;
    float m_a = -INFINITY, m_b = -INFINITY, l_a = 0.f, l_b = 0.f;

    const int ntiles = 2 * m + 2;
    const int wlast  = m * BM + wr0 + 15;

    for (int n = 0; n < ntiles; ++n) {
        __syncthreads();

        // ---- stage K and V (row-major [key][dim], bf16 hi/lo) ----
        const float* kp = k + ((size_t)bh * SEQ + (size_t)n * BKT) * 64;
        const float* vp = v + ((size_t)bh * SEQ + (size_t)n * BKT) * 64;
        #pragma unroll
        for (int i = 0; i < 4; ++i) {
            int lin = tid + i * 256;
            int row = lin >> 4;
            int d4  = (lin & 15) * 4;
            uint32_t off = swz(row, d4 >> 3) + (uint32_t)((d4 & 7) * 2);

            float4 kv = *reinterpret_cast<const float4*>(kp + row * 64 + d4);
            float h0, l0, h1, l1, h2, l2, h3, l3;
            bsplit(kv.x, h0, l0); bsplit(kv.y, h1, l1);
            bsplit(kv.z, h2, l2); bsplit(kv.w, h3, l3);
            *reinterpret_cast<uint2*>(smem + SM_KH + off) = make_uint2(bfpair(h0, h1), bfpair(h2, h3));
            *reinterpret_cast<uint2*>(smem + SM_KL + off) = make_uint2(bfpair(l0, l1), bfpair(l2, l3));

            float4 vv = *reinterpret_cast<const float4*>(vp + row * 64 + d4);
            bsplit(vv.x, h0, l0); bsplit(vv.y, h1, l1);
            bsplit(vv.z, h2, l2); bsplit(vv.w, h3, l3);
            *reinterpret_cast<uint2*>(smem + SM_VH + off) = make_uint2(bfpair(h0, h1), bfpair(h2, h3));
            *reinterpret_cast<uint2*>(smem + SM_VL + off) = make_uint2(bfpair(l0, l1), bfpair(l2, l3));
        }
        __syncthreads();

        const bool active = (n * BKT <= wlast);
        if (active) {
            // bias prefetch (hides under QK MMAs)
            float2 ba[8], bb[8];
            {
                const float* bpa = bias + ((size_t)bh * SEQ + gra) * SEQ + (size_t)n * BKT;
                const float* bpb = bias + ((size_t)bh * SEQ + grb) * SEQ + (size_t)n * BKT;
                #pragma unroll
                for (int nb = 0; nb < 8; ++nb) {
                    ba[nb] = *reinterpret_cast<const float2*>(bpa + nb * 8 + 2 * qd);
                    bb[nb] = *reinterpret_cast<const float2*>(bpb + nb * 8 + 2 * qd);
                }
            }

            // ---- S = Qh*Kh + Qh*Kl + Ql*Kh ----
            #pragma unroll
            for (int nb = 0; nb < 8; ++nb)
                #pragma unroll
                for (int e = 0; e < 4; ++e) s[nb][e] = 0.f;
            #pragma unroll
            for (int kk = 0; kk < 4; ++kk) {
                uint32_t aqh[4], aql[4];
                lda(aqh, sb + SM_QH, wr0, kk, lane);
                lda(aql, sb + SM_QL, wr0, kk, lane);
                #pragma unroll
                for (int nb2 = 0; nb2 < 4; ++nb2) {
                    uint32_t bhf[4], blf[4];
                    ldb(bhf, sb + SM_KH, nb2 * 16, kk, lane);
                    ldb(blf, sb + SM_KL, nb2 * 16, kk, lane);
                    mmabf(s[2 * nb2],     aqh, bhf[0], bhf[1]);
                    mmabf(s[2 * nb2 + 1], aqh, bhf[2], bhf[3]);
                    mmabf(s[2 * nb2],     aqh, blf[0], blf[1]);
                    mmabf(s[2 * nb2 + 1], aqh, blf[2], blf[3]);
                    mmabf(s[2 * nb2],     aql, bhf[0], bhf[1]);
                    mmabf(s[2 * nb2 + 1], aql, bhf[2], bhf[3]);
                }
            }

            // ---- bias + causal mask ----
            const int c00 = n * BKT + 2 * qd;
            #pragma unroll
            for (int nb = 0; nb < 8; ++nb) {
                int c0 = c00 + nb * 8, c1 = c0 + 1;
                s[nb][0] = (c0 <= gra) ? s[nb][0] + ba[nb].x : -INFINITY;
                s[nb][1] = (c1 <= gra) ? s[nb][1] + ba[nb].y : -INFINITY;
                s[nb][2] = (c0 <= grb) ? s[nb][2] + bb[nb].x : -INFINITY;
                s[nb][3] = (c1 <= grb) ? s[nb][3] + bb[nb].y : -INFINITY;
            }

            // ---- online softmax ----
            float tma = -INFINITY, tmb = -INFINITY;
            #pragma unroll
            for (int nb = 0; nb < 8; ++nb) {
                tma = fmaxf(tma, fmaxf(s[nb][0], s[nb][1]));
                tmb = fmaxf(tmb, fmaxf(s[nb][2], s[nb][3]));
            }
            tma = fmaxf(tma, __shfl_xor_sync(0xffffffffu, tma, 1));
            tma = fmaxf(tma, __shfl_xor_sync(0xffffffffu, tma, 2));
            tmb = fmaxf(tmb, __shfl_xor_sync(0xffffffffu, tmb, 1));
            tmb = fmaxf(tmb, __shfl_xor_sync(0xffffffffu, tmb, 2));

            float mna = fmaxf(m_a, tma), mnb = fmaxf(m_b, tmb);
            float ca = __expf(m_a - mna), cb = __expf(m_b - mnb);
            m_a = mna; m_b = mnb;

            float pa = 0.f, pb = 0.f;
            #pragma unroll
            for (int nb = 0; nb < 8; ++nb) {
                float p0 = __expf(s[nb][0] - mna);
                float p1 = __expf(s[nb][1] - mna);
                float p2 = __expf(s[nb][2] - mnb);
                float p3 = __expf(s[nb][3] - mnb);
                s[nb][0] = p0; s[nb][1] = p1; s[nb][2] = p2; s[nb][3] = p3;
                pa += p0 + p1; pb += p2 + p3;
            }
            pa += __shfl_xor_sync(0xffffffffu, pa, 1);
            pa += __shfl_xor_sync(0xffffffffu, pa, 2);
            pb += __shfl_xor_sync(0xffffffffu, pb, 1);
            pb += __shfl_xor_sync(0xffffffffu, pb, 2);
            l_a = l_a * ca + pa;
            l_b = l_b * cb + pb;
            #pragma unroll
            for (int nb = 0; nb < 8; ++nb) {
                o[nb][0] *= ca; o[nb][1] *= ca;
                o[nb][2] *= cb; o[nb][3] *= cb;
            }

            // ---- O += Ph*Vh + Ph*Vl + Pl*Vh ----
            // A-fragments of P come straight from S accumulators:
            // k-block kk covers keys 16kk..16kk+15 = n-blocks 2kk, 2kk+1 of S.
            // a0 = S[2kk][0,1], a1 = S[2kk][2,3], a2 = S[2kk+1][0,1], a3 = S[2kk+1][2,3].
            #pragma unroll
            for (int kk = 0; kk < 4; ++kk) {
                uint32_t aph[4], apl[4];
                #pragma unroll
                for (int half = 0; half < 2; ++half) {
                    const float* sp = s[2 * kk + half];
                    float h0, l0, h1, l1, h2, l2, h3, l3;
                    bsplit(sp[0], h0, l0); bsplit(sp[1], h1, l1);
                    bsplit(sp[2], h2, l2); bsplit(sp[3], h3, l3);
                    aph[2 * half]     = bfpair(h0, h1);
                    aph[2 * half + 1] = bfpair(h2, h3);
                    apl[2 * half]     = bfpair(l0, l1);
                    apl[2 * half + 1] = bfpair(l2, l3);
                }
                #pragma unroll
                for (int nb2 = 0; nb2 < 4; ++nb2) {
                    uint32_t bvh[4], bvl[4];
                    ldbT(bvh, sb + SM_VH, kk, nb2, lane);
                    ldbT(bvl, sb + SM_VL, kk, nb2, lane);
                    mmabf(o[2 * nb2],     aph, bvh[0], bvh[1]);
                    mmabf(o[2 * nb2 + 1], aph, bvh[2], bvh[3]);
                    mmabf(o[2 * nb2],     aph, bvl[0], bvl[1]);
                    mmabf(o[2 * nb2 + 1], aph, bvl[2], bvl[3]);
                    mmabf(o[2 * nb2],     apl, bvh[0], bvh[1]);
                    mmabf(o[2 * nb2 + 1], apl, bvh[2], bvh[3]);
                }
            }
        }
    }

    // ---- epilogue ----
    const float ia = 1.f / l_a, ib = 1.f / l_b;
    float* opa = out + ((size_t)bh * SEQ + gra) * 64;
    float* opb = out + ((size_t)bh * SEQ + grb) * 64;
    #pragma unroll
    for (int nb = 0; nb < 8; ++nb) {
        int col = nb * 8 + 2 * qd;
        *reinterpret_cast<float2*>(opa + col) = make_float2(o[nb][0] * ia, o[nb][1] * ia);
        *reinterpret_cast<float2*>(opb + col) = make_float2(o[nb][2] * ib, o[nb][3] * ib);
    }
}

extern "C" void kernel_launch(void* const* d_in, const int* in_sizes, int n_in,
                              void* d_out, int out_size)
{
    const float* q    = (const float*)d_in[0];
    const float* k    = (const float*)d_in[1];
    const float* v    = (const float*)d_in[2];
    const float* bias = (const float*)d_in[3];
    float* out = (float*)d_out;

    cudaFuncSetAttribute(attn_bf16_kernel,
                         cudaFuncAttributeMaxDynamicSharedMemorySize, SM_TOTAL);
    attn_bf16_kernel<<<512, 256, SM_TOTAL>>>(q, k, v, bias, out);
}

// round 10
// speedup vs baseline: 4.5575x; 1.2553x over previous
#include <cuda_runtime.h>
#include <cuda_fp16.h>
#include <math.h>
#include <stdint.h>

// Flash attention w/ bias + causal, fp32 I/O, fp16 mma.sync (m16n8k16).
// 2 CTAs/SM, 64KB smem, 128-reg cap. Double-buffered K/V, 1 barrier/tile.
// QK = Qh*K + Ql*K (Q hi/lo fp16, K single fp16)
// PV = Ph*V + Pl*V (P hi/lo fp16 from S-regs, V single fp16)

#define SEQ 1024
#define BM  128
#define BKT 64

// smem: Q hi/lo (16KB each), two K/V buffers (K 8KB + V 8KB each)
#define SM_QH  0u
#define SM_QL  16384u
#define SM_KV  32768u
#define KVSZ   16384u
#define KV_K   0u
#define KV_V   8192u
#define SM_TOTAL 65536

static __device__ __forceinline__ uint32_t smem_u32(const void* p) {
    uint32_t a;
    asm("{ .reg .u64 t; cvta.to.shared.u64 t, %1; cvt.u32.u64 %0, t; }" : "=r"(a) : "l"(p));
    return a;
}
// row stride 128B (64 fp16), 16B chunks XOR-swizzled by row
static __device__ __forceinline__ uint32_t swz(int row, int chunk) {
    return (uint32_t)(row * 128 + ((chunk ^ (row & 7)) << 4));
}
static __device__ __forceinline__ uint32_t hpair(float a, float b) {
    __half2 t = __floats2half2_rn(a, b);
    return *reinterpret_cast<uint32_t*>(&t);
}
static __device__ __forceinline__ void ldsm4(uint32_t r[4], uint32_t addr) {
    asm volatile("ldmatrix.sync.aligned.m8n8.x4.shared.b16 {%0,%1,%2,%3}, [%4];"
                 : "=r"(r[0]), "=r"(r[1]), "=r"(r[2]), "=r"(r[3]) : "r"(addr));
}
static __device__ __forceinline__ void ldsm4t(uint32_t r[4], uint32_t addr) {
    asm volatile("ldmatrix.sync.aligned.m8n8.x4.trans.shared.b16 {%0,%1,%2,%3}, [%4];"
                 : "=r"(r[0]), "=r"(r[1]), "=r"(r[2]), "=r"(r[3]) : "r"(addr));
}
static __device__ __forceinline__ void lda(uint32_t a[4], uint32_t tb, int row0, int kk, int lane) {
    int sel = lane >> 3;
    int row = row0 + (lane & 7) + ((sel & 1) << 3);
    int ch  = kk * 2 + (sel >> 1);
    ldsm4(a, tb + swz(row, ch));
}
static __device__ __forceinline__ void ldb(uint32_t b[4], uint32_t tb, int n0, int kk, int lane) {
    int sel = lane >> 3;
    int row = n0 + ((sel >> 1) << 3) + (lane & 7);
    int ch  = kk * 2 + (sel & 1);
    ldsm4(b, tb + swz(row, ch));
}
static __device__ __forceinline__ void ldbT(uint32_t b[4], uint32_t tb, int kk, int nb2, int lane) {
    int sel = lane >> 3;
    int row = kk * 16 + ((sel & 1) << 3) + (lane & 7);
    int ch  = nb2 * 2 + (sel >> 1);
    ldsm4t(b, tb + swz(row, ch));
}
static __device__ __forceinline__ void mmaf16(float c[4], const uint32_t a[4], uint32_t b0, uint32_t b1) {
    asm volatile("mma.sync.aligned.m16n8k16.row.col.f32.f16.f16.f32 "
                 "{%0,%1,%2,%3}, {%4,%5,%6,%7}, {%8,%9}, {%0,%1,%2,%3};"
                 : "+f"(c[0]), "+f"(c[1]), "+f"(c[2]), "+f"(c[3])
                 : "r"(a[0]), "r"(a[1]), "r"(a[2]), "r"(a[3]), "r"(b0), "r"(b1));
}

__global__ __launch_bounds__(256, 2)
void attn_f16_kernel(const float* __restrict__ q,
                     const float* __restrict__ k,
                     const float* __restrict__ v,
                     const float* __restrict__ bias,
                     float* __restrict__ out)
{
    extern __shared__ char smem[];
    const uint32_t sb = smem_u32(smem);
    const int tid  = threadIdx.x;
    const int wid  = tid >> 5;
    const int lane = tid & 31;
    const int qd   = lane & 3;

    const int m  = 7 - (int)(blockIdx.x >> 6);   // heavy CTAs first
    const int bh = (int)(blockIdx.x & 63);

    // ---- prologue: stage Q (scaled, fp16 hi/lo split) ----
    const float* qp = q + ((size_t)bh * SEQ + (size_t)m * BM) * 64;
    #pragma unroll
    for (int i = 0; i < 8; ++i) {
        int lin = tid + i * 256;
        int row = lin >> 4;
        int d4  = (lin & 15) * 4;
        float4 v4 = *reinterpret_cast<const float4*>(qp + row * 64 + d4);
        float xs[4] = {v4.x * 0.125f, v4.y * 0.125f, v4.z * 0.125f, v4.w * 0.125f};
        float h[4], l[4];
        #pragma unroll
        for (int e = 0; e < 4; ++e) {
            __half hh = __float2half_rn(xs[e]);
            h[e] = __half2float(hh);
            l[e] = xs[e] - h[e];
        }
        uint32_t off = swz(row, d4 >> 3) + (uint32_t)((d4 & 7) * 2);
        *reinterpret_cast<uint2*>(smem + SM_QH + off) = make_uint2(hpair(h[0], h[1]), hpair(h[2], h[3]));
        *reinterpret_cast<uint2*>(smem + SM_QL + off) = make_uint2(hpair(l[0], l[1]), hpair(l[2], l[3]));
    }

    const int wr0 = wid * 16;
    const int gra = m * BM + wr0 + (lane >> 2);
    const int grb = gra + 8;

    float s[8][4];
    float o[8][4];
    #pragma unroll
    for (int nb = 0; nb < 8; ++nb)
        #pragma unroll
        for (int e = 0; e < 4; ++e) o[nb][e] = 0.f;
    float m_a = -INFINITY, m_b = -INFINITY, l_a = 0.f, l_b = 0.f;

    const int ntiles = 2 * m + 2;
    const int wlast  = m * BM + wr0 + 15;

    for (int n = 0; n < ntiles; ++n) {
        // ---- stage K and V (single fp16) into buffer n&1 ----
        // (safe: prior reads of this buffer ended before the previous barrier)
        const uint32_t kvb = SM_KV + (uint32_t)(n & 1) * KVSZ;
        const float* kp = k + ((size_t)bh * SEQ + (size_t)n * BKT) * 64;
        const float* vp = v + ((size_t)bh * SEQ + (size_t)n * BKT) * 64;
        #pragma unroll
        for (int i = 0; i < 4; ++i) {
            int lin = tid + i * 256;
            int row = lin >> 4;
            int d4  = (lin & 15) * 4;
            uint32_t off = swz(row, d4 >> 3) + (uint32_t)((d4 & 7) * 2);
            float4 kv = *reinterpret_cast<const float4*>(kp + row * 64 + d4);
            *reinterpret_cast<uint2*>(smem + kvb + KV_K + off) =
                make_uint2(hpair(kv.x, kv.y), hpair(kv.z, kv.w));
            float4 vv = *reinterpret_cast<const float4*>(vp + row * 64 + d4);
            *reinterpret_cast<uint2*>(smem + kvb + KV_V + off) =
                make_uint2(hpair(vv.x, vv.y), hpair(vv.z, vv.w));
        }
        __syncthreads();   // single barrier per tile

        const bool active = (n * BKT <= wlast);
        if (active) {
            const uint32_t KB = sb + kvb + KV_K;
            const uint32_t VB = sb + kvb + KV_V;

            // bias prefetch (hides under QK MMAs)
            float2 ba[8], bb[8];
            {
                const float* bpa = bias + ((size_t)bh * SEQ + gra) * SEQ + (size_t)n * BKT;
                const float* bpb = bias + ((size_t)bh * SEQ + grb) * SEQ + (size_t)n * BKT;
                #pragma unroll
                for (int nb = 0; nb < 8; ++nb) {
                    ba[nb] = *reinterpret_cast<const float2*>(bpa + nb * 8 + 2 * qd);
                    bb[nb] = *reinterpret_cast<const float2*>(bpb + nb * 8 + 2 * qd);
                }
            }

            // ---- S = Qh*K + Ql*K ----
            #pragma unroll
            for (int nb = 0; nb < 8; ++nb)
                #pragma unroll
                for (int e = 0; e < 4; ++e) s[nb][e] = 0.f;
            #pragma unroll
            for (int kk = 0; kk < 4; ++kk) {
                uint32_t aqh[4], aql[4];
                lda(aqh, sb + SM_QH, wr0, kk, lane);
                lda(aql, sb + SM_QL, wr0, kk, lane);
                #pragma unroll
                for (int nb2 = 0; nb2 < 4; ++nb2) {
                    uint32_t bk[4];
                    ldb(bk, KB, nb2 * 16, kk, lane);
                    mmaf16(s[2 * nb2],     aqh, bk[0], bk[1]);
                    mmaf16(s[2 * nb2 + 1], aqh, bk[2], bk[3]);
                    mmaf16(s[2 * nb2],     aql, bk[0], bk[1]);
                    mmaf16(s[2 * nb2 + 1], aql, bk[2], bk[3]);
                }
            }

            // ---- bias + causal mask ----
            const int c00 = n * BKT + 2 * qd;
            #pragma unroll
            for (int nb = 0; nb < 8; ++nb) {
                int c0 = c00 + nb * 8, c1 = c0 + 1;
                s[nb][0] = (c0 <= gra) ? s[nb][0] + ba[nb].x : -INFINITY;
                s[nb][1] = (c1 <= gra) ? s[nb][1] + ba[nb].y : -INFINITY;
                s[nb][2] = (c0 <= grb) ? s[nb][2] + bb[nb].x : -INFINITY;
                s[nb][3] = (c1 <= grb) ? s[nb][3] + bb[nb].y : -INFINITY;
            }

            // ---- online softmax ----
            float tma = -INFINITY, tmb = -INFINITY;
            #pragma unroll
            for (int nb = 0; nb < 8; ++nb) {
                tma = fmaxf(tma, fmaxf(s[nb][0], s[nb][1]));
                tmb = fmaxf(tmb, fmaxf(s[nb][2], s[nb][3]));
            }
            tma = fmaxf(tma, __shfl_xor_sync(0xffffffffu, tma, 1));
            tma = fmaxf(tma, __shfl_xor_sync(0xffffffffu, tma, 2));
            tmb = fmaxf(tmb, __shfl_xor_sync(0xffffffffu, tmb, 1));
            tmb = fmaxf(tmb, __shfl_xor_sync(0xffffffffu, tmb, 2));

            float mna = fmaxf(m_a, tma), mnb = fmaxf(m_b, tmb);
            float ca = __expf(m_a - mna), cb = __expf(m_b - mnb);
            m_a = mna; m_b = mnb;

            float pa = 0.f, pb = 0.f;
            #pragma unroll
            for (int nb = 0; nb < 8; ++nb) {
                float p0 = __expf(s[nb][0] - mna);
                float p1 = __expf(s[nb][1] - mna);
                float p2 = __expf(s[nb][2] - mnb);
                float p3 = __expf(s[nb][3] - mnb);
                s[nb][0] = p0; s[nb][1] = p1; s[nb][2] = p2; s[nb][3] = p3;
                pa += p0 + p1; pb += p2 + p3;
            }
            pa += __shfl_xor_sync(0xffffffffu, pa, 1);
            pa += __shfl_xor_sync(0xffffffffu, pa, 2);
            pb += __shfl_xor_sync(0xffffffffu, pb, 1);
            pb += __shfl_xor_sync(0xffffffffu, pb, 2);
            l_a = l_a * ca + pa;
            l_b = l_b * cb + pb;
            #pragma unroll
            for (int nb = 0; nb < 8; ++nb) {
                o[nb][0] *= ca; o[nb][1] *= ca;
                o[nb][2] *= cb; o[nb][3] *= cb;
            }

            // ---- O += Ph*V + Pl*V (P hi/lo fp16 straight from S regs) ----
            #pragma unroll
            for (int kk = 0; kk < 4; ++kk) {
                uint32_t aph[4], apl[4];
                #pragma unroll
                for (int half = 0; half < 2; ++half) {
                    const float* sp = s[2 * kk + half];
                    float h[4], l[4];
                    #pragma unroll
                    for (int e = 0; e < 4; ++e) {
                        __half hh = __float2half_rn(sp[e]);
                        h[e] = __half2float(hh);
                        l[e] = sp[e] - h[e];
                    }
                    aph[2 * half]     = hpair(h[0], h[1]);
                    aph[2 * half + 1] = hpair(h[2], h[3]);
                    apl[2 * half]     = hpair(l[0], l[1]);
                    apl[2 * half + 1] = hpair(l[2], l[3]);
                }
                #pragma unroll
                for (int nb2 = 0; nb2 < 4; ++nb2) {
                    uint32_t bv[4];
                    ldbT(bv, VB, kk, nb2, lane);
                    mmaf16(o[2 * nb2],     aph, bv[0], bv[1]);
                    mmaf16(o[2 * nb2 + 1], aph, bv[2], bv[3]);
                    mmaf16(o[2 * nb2],     apl, bv[0], bv[1]);
                    mmaf16(o[2 * nb2 + 1], apl, bv[2], bv[3]);
                }
            }
        }
    }

    // ---- epilogue ----
    const float ia = 1.f / l_a, ib = 1.f / l_b;
    float* opa = out + ((size_t)bh * SEQ + gra) * 64;
    float* opb = out + ((size_t)bh * SEQ + grb) * 64;
    #pragma unroll
    for (int nb = 0; nb < 8; ++nb) {
        int col = nb * 8 + 2 * qd;
        *reinterpret_cast<float2*>(opa + col) = make_float2(o[nb][0] * ia, o[nb][1] * ia);
        *reinterpret_cast<float2*>(opb + col) = make_float2(o[nb][2] * ib, o[nb][3] * ib);
    }
}

extern "C" void kernel_launch(void* const* d_in, const int* in_sizes, int n_in,
                              void* d_out, int out_size)
{
    const float* q    = (const float*)d_in[0];
    const float* k    = (const float*)d_in[1];
    const float* v    = (const float*)d_in[2];
    const float* bias = (const float*)d_in[3];
    float* out = (float*)d_out;

    cudaFuncSetAttribute(attn_f16_kernel,
                         cudaFuncAttributeMaxDynamicSharedMemorySize, SM_TOTAL);
    attn_f16_kernel<<<512, 256, SM_TOTAL>>>(q, k, v, bias, out);
}